// round 7
// baseline (speedup 1.0000x reference)
#include <cuda_runtime.h>
#include <cuda_fp16.h>
#include <math.h>
#include <stdint.h>

// ---------------- constants ----------------
#define kS   1024
#define kD   2048
#define kH   32
#define kHD  64
#define kF   8192
#define kNE  4
#define kVOC 50257

// ---------------- scratch ----------------
__device__ __half g_x0h [kS*kD];
__device__ __half g_qkvh[kS*3*kD];
__device__ __half g_oh  [kS*kD];
__device__ __half g_xn1h[kS*kD];
__device__ __half g_hah [kS*kNE*kF];
__device__ __half g_hbh [kS*kNE*kF];
__device__ __half g_x4h [kS*kD];
__device__ float g_part[2*kS*3*kD];
__device__ float g_x1 [kS*kD];
__device__ float g_x2 [kS*kD];
__device__ float g_wdense[kS*kNE];
__device__ float g_var[kS];

// ---------------- PTX helpers ----------------
__device__ __forceinline__ uint32_t smem_u32(const void* p) {
    uint32_t a;
    asm("{ .reg .u64 t; cvta.to.shared.u64 t, %1; cvt.u32.u64 %0, t; }" : "=r"(a) : "l"(p));
    return a;
}
__device__ __forceinline__ void cpa16(uint32_t dst, const void* src) {
    asm volatile("cp.async.cg.shared.global [%0], [%1], 16;" :: "r"(dst), "l"(src));
}
#define CPA_COMMIT() asm volatile("cp.async.commit_group;" ::: "memory")
#define CPA_WAIT2()  asm volatile("cp.async.wait_group 2;" ::: "memory")

#define LDSM_X4(r, addr) \
    asm volatile("ldmatrix.sync.aligned.m8n8.x4.shared.b16 {%0,%1,%2,%3}, [%4];" \
        : "=r"((r)[0]), "=r"((r)[1]), "=r"((r)[2]), "=r"((r)[3]) : "r"(addr))

__device__ __forceinline__ void mma_f16(float* c, const uint32_t* a, uint32_t b0, uint32_t b1) {
    asm volatile("mma.sync.aligned.m16n8k16.row.col.f32.f16.f16.f32 "
        "{%0,%1,%2,%3}, {%4,%5,%6,%7}, {%8,%9}, {%0,%1,%2,%3};"
        : "+f"(c[0]), "+f"(c[1]), "+f"(c[2]), "+f"(c[3])
        : "r"(a[0]), "r"(a[1]), "r"(a[2]), "r"(a[3]), "r"(b0), "r"(b1));
}

// ---------------- fp16-A x fp32-B mma.sync NT GEMM ----------------
// C[m,n] = sum_k A[m,k]*half(B(n,k)); A half via cp.async, B fp32 via LDG->cvt->STS.
// B segment select: nShift (along n) or kShift (along 64-k tiles).
// Output: Ch (half) if nonnull else Cf (fp32, split-K via blockIdx.z partials).
// fmode 2: C = half( wdense[m, n>>13] * silu(F[m,n]) * acc )
#define BM 128
#define BN 128
#define BKH 64
#define NSTG 4
#define ASTG 16384
#define STGB 32768
#define GEMM_SMEM (NSTG*STGB)

__global__ void __launch_bounds__(256, 1) gemm_hw(
    const __half* __restrict__ A,
    const float* __restrict__ B0, const float* __restrict__ B1,
    const float* __restrict__ B2, const float* __restrict__ B3,
    float* __restrict__ Cf, __half* __restrict__ Ch,
    int N, int KT, int ldA, int ldB, int ldC,
    int nShift, int kShift, int ktPerZ, long long zStrideC,
    int fmode, const __half* __restrict__ F, int ldF,
    const float* __restrict__ wdense)
{
    extern __shared__ char smc[];
    uint32_t sb = smem_u32(smc);
    int tid = threadIdx.x, lane = tid & 31, wid = tid >> 5;
    int wm = wid >> 2, wn = wid & 3;
    int bm = blockIdx.x * BM, bn = blockIdx.y * BN;

    Cf += (long long)blockIdx.z * zStrideC;
    int ktBeg = blockIdx.z * ktPerZ;
    int KTz = KT - ktBeg; if (KTz > ktPerZ) KTz = ktPerZ;

    const float* BnBase;
    {
        int seg = bn >> nShift;
        const float* bp = (seg == 0) ? B0 : (seg == 1) ? B1 : (seg == 2) ? B2 : B3;
        BnBase = bp + (size_t)(bn - (seg << nShift)) * ldB;
    }

    int ldRow = tid >> 3, ldC8 = tid & 7;   // this thread's 4 (row, chunk) pairs: row += 32*j

    // B global load: 8x LDG.128 fp32 into regs
    auto ldgB = [&](float4* bb, int kt) {
        int ktl = kt;
        const float* Bb = BnBase;
        if (kShift >= 0) {
            int seg = kt >> kShift;
            const float* bp = (seg == 0) ? B0 : (seg == 1) ? B1 : (seg == 2) ? B2 : B3;
            ktl = kt - (seg << kShift);
            Bb = bp + (size_t)bn * ldB;
        }
#pragma unroll
        for (int j = 0; j < 4; j++) {
            int row = ldRow + j * 32;
            if (bn + row < N) {
                const float* src = Bb + (size_t)row * ldB + ktl * BKH + ldC8 * 8;
                bb[2 * j]     = *(const float4*)src;
                bb[2 * j + 1] = *(const float4*)(src + 4);
            }
        }
    };
    // B smem store: convert + STS.128 (swizzled fp16 layout identical to A's)
    auto stsB = [&](const float4* bb, int s) {
#pragma unroll
        for (int j = 0; j < 4; j++) {
            int row = ldRow + j * 32;
            uint32_t off = (uint32_t)s * STGB + ASTG
                         + (uint32_t)(row << 7) + ((uint32_t)(ldC8 ^ (row & 7)) << 4);
            __half2 h0 = __floats2half2_rn(bb[2 * j].x, bb[2 * j].y);
            __half2 h1 = __floats2half2_rn(bb[2 * j].z, bb[2 * j].w);
            __half2 h2 = __floats2half2_rn(bb[2 * j + 1].x, bb[2 * j + 1].y);
            __half2 h3 = __floats2half2_rn(bb[2 * j + 1].z, bb[2 * j + 1].w);
            uint4 pk;
            pk.x = *reinterpret_cast<uint32_t*>(&h0);
            pk.y = *reinterpret_cast<uint32_t*>(&h1);
            pk.z = *reinterpret_cast<uint32_t*>(&h2);
            pk.w = *reinterpret_cast<uint32_t*>(&h3);
            *(uint4*)(smc + off) = pk;
        }
    };
    // A smem load via cp.async
    auto cpaA = [&](int s, int kt) {
#pragma unroll
        for (int j = 0; j < 4; j++) {
            int row = ldRow + j * 32;
            uint32_t dst = sb + (uint32_t)s * STGB
                         + (uint32_t)(row << 7) + ((uint32_t)(ldC8 ^ (row & 7)) << 4);
            cpa16(dst, A + (size_t)(bm + row) * ldA + kt * BKH + ldC8 * 8);
        }
    };

    float acc[4][4][4];
#pragma unroll
    for (int i = 0; i < 4; i++)
#pragma unroll
        for (int j = 0; j < 4; j++)
#pragma unroll
            for (int r = 0; r < 4; r++) acc[i][j][r] = 0.0f;

    // ldmatrix lane geometry (fp16)
    int l7 = lane & 7;
    int sub = lane >> 3;
    int arow = (sub & 1) * 8 + l7;
    int ah   = sub >> 1;
    int bnl  = (sub >> 1) * 8 + l7;
    int bch  = sub & 1;
    uint32_t aBase = sb + (uint32_t)((wm * 64 + arow) << 7);
    uint32_t bBase = sb + ASTG + (uint32_t)((wn * 32 + bnl) << 7);

    float4 bbuf[8];
    // prologue: B(0) direct, A stages 0..2
    ldgB(bbuf, ktBeg);
    stsB(bbuf, 0);
#pragma unroll
    for (int s = 0; s < NSTG - 1; s++) {
        if (s < KTz) cpaA(s, ktBeg + s);
        CPA_COMMIT();
    }

    for (int t = 0; t < KTz; t++) {
        int slot = t & (NSTG - 1);
        CPA_WAIT2();
        __syncthreads();
        if (t + 1 < KTz) ldgB(bbuf, ktBeg + t + 1);
        int tn = t + NSTG - 1;
        if (tn < KTz) cpaA(tn & (NSTG - 1), ktBeg + tn);
        CPA_COMMIT();

        uint32_t aS = aBase + (uint32_t)slot * STGB;
        uint32_t bS = bBase + (uint32_t)slot * STGB;
#pragma unroll
        for (int ks = 0; ks < 4; ks++) {
            uint32_t bf[2][4];
            uint32_t af[4][4];
#pragma unroll
            for (int ntp = 0; ntp < 2; ntp++)
                LDSM_X4(bf[ntp], bS + (uint32_t)(ntp * 2048) +
                                  ((uint32_t)((2 * ks + bch) ^ l7) << 4));
#pragma unroll
            for (int mt = 0; mt < 4; mt++)
                LDSM_X4(af[mt], aS + (uint32_t)(mt * 2048) +
                                 ((uint32_t)((2 * ks + ah) ^ l7) << 4));
#pragma unroll
            for (int mt = 0; mt < 4; mt++)
#pragma unroll
                for (int nt = 0; nt < 4; nt++)
                    mma_f16(acc[mt][nt], af[mt],
                            bf[nt >> 1][(nt & 1) * 2], bf[nt >> 1][(nt & 1) * 2 + 1]);
        }
        if (t + 1 < KTz) stsB(bbuf, (t + 1) & (NSTG - 1));
    }

    // epilogue
    int evenN = ((N & 1) == 0);
#pragma unroll
    for (int mt = 0; mt < 4; mt++) {
        int r0 = bm + wm * 64 + mt * 16 + (lane >> 2);
        int r1 = r0 + 8;
#pragma unroll
        for (int nt = 0; nt < 4; nt++) {
            int n0 = bn + wn * 32 + nt * 8 + 2 * (lane & 3);
            const float* a = acc[mt][nt];
            float v00 = a[0], v01 = a[1], v10 = a[2], v11 = a[3];
            if (fmode == 2) {
                float2 f0 = __half22float2(*(const __half2*)(F + (size_t)r0 * ldF + n0));
                float2 f1 = __half22float2(*(const __half2*)(F + (size_t)r1 * ldF + n0));
                int e = n0 >> 13;
                float w0 = wdense[r0 * 4 + e], w1_ = wdense[r1 * 4 + e];
                v00 = w0 * (f0.x / (1.0f + __expf(-f0.x))) * v00;
                v01 = w0 * (f0.y / (1.0f + __expf(-f0.y))) * v01;
                v10 = w1_ * (f1.x / (1.0f + __expf(-f1.x))) * v10;
                v11 = w1_ * (f1.y / (1.0f + __expf(-f1.y))) * v11;
            }
            if (Ch) {
                *(__half2*)(Ch + (size_t)r0 * ldC + n0) = __floats2half2_rn(v00, v01);
                *(__half2*)(Ch + (size_t)r1 * ldC + n0) = __floats2half2_rn(v10, v11);
            } else if (evenN && n0 + 1 < N) {
                *(float2*)(Cf + (size_t)r0 * ldC + n0) = make_float2(v00, v01);
                *(float2*)(Cf + (size_t)r1 * ldC + n0) = make_float2(v10, v11);
            } else {
                if (n0 < N)     { Cf[(size_t)r0 * ldC + n0] = v00; Cf[(size_t)r1 * ldC + n0] = v10; }
                if (n0 + 1 < N) { Cf[(size_t)r0 * ldC + n0 + 1] = v01; Cf[(size_t)r1 * ldC + n0 + 1] = v11; }
            }
        }
    }
}

// ---------------- embed (half out) ----------------
__global__ void embed_kernel(const int* __restrict__ tok, const float* __restrict__ emb,
                             __half* __restrict__ X) {
    int i = blockIdx.x * blockDim.x + threadIdx.x;
    int t = i >> 11;
    int d = i & 2047;
    X[i] = __float2half_rn(emb[(size_t)tok[t] * kD + d]);
}

// ---------------- RoPE on packed half QKV ----------------
__global__ void rope_kernel(__half* __restrict__ X) {
    int i = blockIdx.x * blockDim.x + threadIdx.x;   // [0, 2*kS*kH*32)
    int sel = i & 1;
    int j = i >> 1;
    int p = j & 31;
    int h = (j >> 5) & 31;
    int t = j >> 10;
    float inv = 1.0f / powf(10000.0f, (float)(2 * p) / 64.0f);
    float ang = (float)t * inv;
    float c = cosf(ang), s = sinf(ang);
    size_t base = (size_t)t * (3 * kD) + sel * kD + h * kHD + 2 * p;
    __half2* px = (__half2*)(X + base);
    float2 x = __half22float2(*px);
    *px = __floats2half2_rn(x.x * c - x.y * s, x.x * s + x.y * c);
}

// ---------------- attention (fp32 compute, half IO, parallel softmax) ----------------
__global__ void attn_kernel(const __half* __restrict__ QKV, __half* __restrict__ O) {
    extern __shared__ float sm[];
    const int LD = 68;
    const int ldx = 3 * kD;
    float* Qt  = sm;
    float* KP  = Qt + 64 * LD;
    float* Vs  = KP + 64 * LD;
    float* den = Vs + 64 * LD;
    int qi = blockIdx.x;
    int h  = blockIdx.y;
    int tid = threadIdx.x;
    int tx = tid & 15, ty = tid >> 4;

    for (int it = tid; it < 512; it += 256) {
        int q = it >> 3;
        int c8 = (it & 7) << 3;
        uint4 raw = *(const uint4*)(QKV + (size_t)(qi * 64 + q) * ldx + h * kHD + c8);
        const __half2* hp = (const __half2*)&raw;
#pragma unroll
        for (int m = 0; m < 4; m++) {
            float2 f = __half22float2(hp[m]);
            Qt[(c8 + 2 * m) * LD + q] = f.x;
            Qt[(c8 + 2 * m + 1) * LD + q] = f.y;
        }
    }
    if (tid < 64) den[tid] = 0.0f;

    float o[4][4] = {};
    for (int j = 0; j <= qi; j++) {
        __syncthreads();
        for (int it = tid; it < 512; it += 256) {
            int r = it >> 3;
            int c8 = (it & 7) << 3;
            uint4 kraw = *(const uint4*)(QKV + kD + (size_t)(j * 64 + r) * ldx + h * kHD + c8);
            uint4 vraw = *(const uint4*)(QKV + 2 * kD + (size_t)(j * 64 + r) * ldx + h * kHD + c8);
            const __half2* kp = (const __half2*)&kraw;
            const __half2* vp = (const __half2*)&vraw;
#pragma unroll
            for (int m = 0; m < 4; m++) {
                float2 fk = __half22float2(kp[m]);
                KP[(c8 + 2 * m) * LD + r] = fk.x;
                KP[(c8 + 2 * m + 1) * LD + r] = fk.y;
                float2 fv = __half22float2(vp[m]);
                Vs[r * LD + c8 + 2 * m] = fv.x;
                Vs[r * LD + c8 + 2 * m + 1] = fv.y;
            }
        }
        __syncthreads();
        float s[4][4] = {};
#pragma unroll 8
        for (int d = 0; d < 64; d++) {
            float4 a = *(const float4*)&Qt[d * LD + (ty << 2)];
            float4 b = *(const float4*)&KP[d * LD + (tx << 2)];
            float av[4] = {a.x, a.y, a.z, a.w};
            float bv[4] = {b.x, b.y, b.z, b.w};
#pragma unroll
            for (int i = 0; i < 4; i++)
#pragma unroll
                for (int j2 = 0; j2 < 4; j2++) s[i][j2] += av[i] * bv[j2];
        }
        __syncthreads();
#pragma unroll
        for (int i = 0; i < 4; i++) {
#pragma unroll
            for (int j2 = 0; j2 < 4; j2++) {
                int q = ty * 4 + i;
                int kcol = tx * 4 + j2;
                float val = s[i][j2] * 0.125f;
                if (j == qi && kcol > q) val = -INFINITY;
                KP[kcol * LD + q] = val;
            }
        }
        __syncthreads();
        {
            int q = tid >> 2, part = tid & 3;
            float m = -INFINITY;
#pragma unroll
            for (int i = 0; i < 16; i++)
                m = fmaxf(m, KP[(part + 4 * i) * LD + q]);
            m = fmaxf(m, __shfl_xor_sync(0xFFFFFFFFu, m, 1));
            m = fmaxf(m, __shfl_xor_sync(0xFFFFFFFFu, m, 2));
            float ds = 0.0f;
#pragma unroll
            for (int i = 0; i < 16; i++) {
                int k2 = part + 4 * i;
                float p = __expf(KP[k2 * LD + q] - m);
                KP[k2 * LD + q] = p;
                ds += p;
            }
            ds += __shfl_xor_sync(0xFFFFFFFFu, ds, 1);
            ds += __shfl_xor_sync(0xFFFFFFFFu, ds, 2);
            if (part == 0) den[q] += ds;
        }
        __syncthreads();
#pragma unroll 8
        for (int k2 = 0; k2 < 64; k2++) {
            float4 a = *(const float4*)&KP[k2 * LD + (ty << 2)];
            float4 b = *(const float4*)&Vs[k2 * LD + (tx << 2)];
            float av[4] = {a.x, a.y, a.z, a.w};
            float bv[4] = {b.x, b.y, b.z, b.w};
#pragma unroll
            for (int i = 0; i < 4; i++)
#pragma unroll
                for (int j2 = 0; j2 < 4; j2++) o[i][j2] += av[i] * bv[j2];
        }
    }
    __syncthreads();
#pragma unroll
    for (int i = 0; i < 4; i++) {
        int q = ty * 4 + i;
        float dn = den[q] + 1e-6f;
#pragma unroll
        for (int j2 = 0; j2 < 4; j2++) {
            int d = tx * 4 + j2;
            O[(size_t)(qi * 64 + q) * kD + h * kHD + d] = __float2half_rn(o[i][j2] / dn);
        }
    }
}

// ---------------- split-K reduce: v = P[i] + P[n+i] (+ half residual) ----------------
__global__ void reduce_k(const float* __restrict__ P, const __half* __restrict__ R,
                         float* __restrict__ Cf, __half* __restrict__ Ch, int n) {
    int i = blockIdx.x * blockDim.x + threadIdx.x;
    if (i < n) {
        float v = P[i] + P[(size_t)n + i];
        if (R) v += __half2float(R[i]);
        if (Ch) Ch[i] = __float2half_rn(v);
        else    Cf[i] = v;
    }
}

// ---------------- layernorm (fp32 in, half out) ----------------
__global__ void ln_kernel(const float* __restrict__ X, const float* __restrict__ g,
                          const float* __restrict__ b, __half* __restrict__ Y) {
    int row = blockIdx.x;
    int tid = threadIdx.x;
    __shared__ float red[256];
    __shared__ float s_mu, s_inv;
    const float* x = X + (size_t)row * kD;
    float s = 0.0f;
    for (int i = tid; i < kD; i += 256) s += x[i];
    red[tid] = s; __syncthreads();
    for (int st = 128; st > 0; st >>= 1) { if (tid < st) red[tid] += red[tid + st]; __syncthreads(); }
    if (tid == 0) s_mu = red[0] / (float)kD;
    __syncthreads();
    float mu = s_mu;
    float v = 0.0f;
    for (int i = tid; i < kD; i += 256) { float d = x[i] - mu; v += d * d; }
    red[tid] = v; __syncthreads();
    for (int st = 128; st > 0; st >>= 1) { if (tid < st) red[tid] += red[tid + st]; __syncthreads(); }
    if (tid == 0) s_inv = 1.0f / sqrtf(red[0] / (float)kD + 1e-5f);
    __syncthreads();
    float inv = s_inv;
    for (int i = tid; i < kD; i += 256)
        Y[(size_t)row * kD + i] = __float2half_rn((x[i] - mu) * inv * g[i] + b[i]);
}

// ---------------- fused double layernorm (fp32 in, half out) ----------------
__global__ void ln2x_kernel(const float* __restrict__ X,
                            const float* __restrict__ g2, const float* __restrict__ b2,
                            const float* __restrict__ gf, const float* __restrict__ bf,
                            __half* __restrict__ Y) {
    int row = blockIdx.x;
    int tid = threadIdx.x;
    __shared__ float red[256];
    __shared__ float s_mu, s_inv;
    __shared__ float buf[kD];
    const float* x = X + (size_t)row * kD;
    float s = 0.0f;
    for (int i = tid; i < kD; i += 256) s += x[i];
    red[tid] = s; __syncthreads();
    for (int st = 128; st > 0; st >>= 1) { if (tid < st) red[tid] += red[tid + st]; __syncthreads(); }
    if (tid == 0) s_mu = red[0] / (float)kD;
    __syncthreads();
    float mu = s_mu;
    float v = 0.0f;
    for (int i = tid; i < kD; i += 256) { float d = x[i] - mu; v += d * d; }
    red[tid] = v; __syncthreads();
    for (int st = 128; st > 0; st >>= 1) { if (tid < st) red[tid] += red[tid + st]; __syncthreads(); }
    if (tid == 0) s_inv = 1.0f / sqrtf(red[0] / (float)kD + 1e-5f);
    __syncthreads();
    float inv = s_inv;
    for (int i = tid; i < kD; i += 256)
        buf[i] = (x[i] - mu) * inv * g2[i] + b2[i];
    __syncthreads();
    s = 0.0f;
    for (int i = tid; i < kD; i += 256) s += buf[i];
    red[tid] = s; __syncthreads();
    for (int st = 128; st > 0; st >>= 1) { if (tid < st) red[tid] += red[tid + st]; __syncthreads(); }
    if (tid == 0) s_mu = red[0] / (float)kD;
    __syncthreads();
    mu = s_mu;
    v = 0.0f;
    for (int i = tid; i < kD; i += 256) { float d = buf[i] - mu; v += d * d; }
    red[tid] = v; __syncthreads();
    for (int st = 128; st > 0; st >>= 1) { if (tid < st) red[tid] += red[tid + st]; __syncthreads(); }
    if (tid == 0) s_inv = 1.0f / sqrtf(red[0] / (float)kD + 1e-5f);
    __syncthreads();
    inv = s_inv;
    for (int i = tid; i < kD; i += 256)
        Y[(size_t)row * kD + i] = __float2half_rn((buf[i] - mu) * inv * gf[i] + bf[i]);
}

// ---------------- gate (half X) ----------------
__global__ void gate_kernel(const __half* __restrict__ X, const float* __restrict__ GW,
                            float* __restrict__ wdense, float* __restrict__ varbuf) {
    int t = blockIdx.x;
    int tid = threadIdx.x;
    __shared__ float red[128];
    __shared__ float logits[4];
    const __half* x = X + (size_t)t * kD;
    float acc[4] = {0.f, 0.f, 0.f, 0.f};
    for (int d = tid; d < kD; d += 128) {
        float xv = __half2float(x[d]);
        acc[0] += xv * GW[0 * kD + d];
        acc[1] += xv * GW[1 * kD + d];
        acc[2] += xv * GW[2 * kD + d];
        acc[3] += xv * GW[3 * kD + d];
    }
    for (int e = 0; e < 4; e++) {
        red[tid] = acc[e]; __syncthreads();
        for (int st = 64; st > 0; st >>= 1) { if (tid < st) red[tid] += red[tid + st]; __syncthreads(); }
        if (tid == 0) logits[e] = red[0];
        __syncthreads();
    }
    if (tid == 0) {
        float l[4] = {logits[0], logits[1], logits[2], logits[3]};
        float mx = fmaxf(fmaxf(l[0], l[1]), fmaxf(l[2], l[3]));
        float pe[4], ps = 0.f;
        for (int e = 0; e < 4; e++) { pe[e] = expf(l[e] - mx); ps += pe[e]; }
        float pr[4];
        for (int e = 0; e < 4; e++) pr[e] = pe[e] / ps;
        int a = 0;
        for (int e = 1; e < 4; e++) if (pr[e] > pr[a]) a = e;
        int b2 = -1;
        for (int e = 0; e < 4; e++) { if (e == a) continue; if (b2 < 0 || pr[e] > pr[b2]) b2 = e; }
        float wsum = pr[a] + pr[b2];
        float w[4] = {0.f, 0.f, 0.f, 0.f};
        w[a] = pr[a] / wsum; w[b2] = pr[b2] / wsum;
        for (int e = 0; e < 4; e++) wdense[t * 4 + e] = w[e];
        float mu = 0.25f * (l[0] + l[1] + l[2] + l[3]);
        float vv = 0.f;
        for (int e = 0; e < 4; e++) { float d = l[e] - mu; vv += d * d; }
        varbuf[t] = vv / 3.0f;
    }
}

__global__ void aux_kernel(const float* __restrict__ varbuf, float* __restrict__ out) {
    __shared__ float red[256];
    int tid = threadIdx.x;
    float s = 0.f;
    for (int i = tid; i < kS; i += 256) s += varbuf[i];
    red[tid] = s; __syncthreads();
    for (int st = 128; st > 0; st >>= 1) { if (tid < st) red[tid] += red[tid + st]; __syncthreads(); }
    if (tid == 0) out[0] = red[0] / (float)kS;
}

// ---------------- launch ----------------
extern "C" void kernel_launch(void* const* d_in, const int* in_sizes, int n_in,
                              void* d_out, int out_size) {
    const int*   tokens = (const int*)d_in[0];
    const float* emb    = (const float*)d_in[1];
    const float* wq     = (const float*)d_in[2];
    const float* wk     = (const float*)d_in[3];
    const float* wv     = (const float*)d_in[4];
    const float* wo     = (const float*)d_in[5];
    const float* ln1_g  = (const float*)d_in[6];
    const float* ln1_b  = (const float*)d_in[7];
    const float* gate_w = (const float*)d_in[8];
    const float* w1     = (const float*)d_in[9];
    const float* w2     = (const float*)d_in[10];
    const float* w3     = (const float*)d_in[11];
    const float* ln2_g  = (const float*)d_in[12];
    const float* ln2_b  = (const float*)d_in[13];
    const float* fin_g  = (const float*)d_in[14];
    const float* fin_b  = (const float*)d_in[15];
    const float* head_w = (const float*)d_in[16];
    float* out = (float*)d_out;

    __half *x0h, *qkvh, *oh, *xn1h, *hah, *hbh, *x4h;
    float *part, *x1, *x2, *wdense, *varbuf;
    cudaGetSymbolAddress((void**)&x0h,  g_x0h);
    cudaGetSymbolAddress((void**)&qkvh, g_qkvh);
    cudaGetSymbolAddress((void**)&oh,   g_oh);
    cudaGetSymbolAddress((void**)&xn1h, g_xn1h);
    cudaGetSymbolAddress((void**)&hah,  g_hah);
    cudaGetSymbolAddress((void**)&hbh,  g_hbh);
    cudaGetSymbolAddress((void**)&x4h,  g_x4h);
    cudaGetSymbolAddress((void**)&part, g_part);
    cudaGetSymbolAddress((void**)&x1,  g_x1);
    cudaGetSymbolAddress((void**)&x2,  g_x2);
    cudaGetSymbolAddress((void**)&wdense, g_wdense);
    cudaGetSymbolAddress((void**)&varbuf, g_var);

    const int SD = kS * kD;
    const int KFD = kF * kD;

    cudaFuncSetAttribute(gemm_hw, cudaFuncAttributeMaxDynamicSharedMemorySize, GEMM_SMEM);

    // embed
    embed_kernel<<<SD / 256, 256>>>(tokens, emb, x0h);

    // QKV (split-K=2 -> fp32 partials -> half qkv)
    gemm_hw<<<dim3(kS / 128, 48, 2), 256, GEMM_SMEM>>>(
        x0h, wq, wk, wv, nullptr, part, nullptr,
        3 * kD, kD / BKH, kD, kD, 3 * kD,
        11, -1, kD / BKH / 2, (long long)kS * 3 * kD,
        0, nullptr, 0, nullptr);
    reduce_k<<<(kS * 3 * kD + 255) / 256, 256>>>(part, nullptr, nullptr, qkvh, kS * 3 * kD);

    // rope
    rope_kernel<<<(2 * kS * kH * 32) / 256, 256>>>(qkvh);

    // attention
    int attn_smem = (3 * 64 * 68 + 64) * (int)sizeof(float);
    cudaFuncSetAttribute(attn_kernel, cudaFuncAttributeMaxDynamicSharedMemorySize, attn_smem);
    attn_kernel<<<dim3(kS / 64, kH), 256, attn_smem>>>(qkvh, oh);

    // wo (split-K=2) -> partials; reduce with x0 residual -> x1 fp32
    gemm_hw<<<dim3(kS / 128, kD / 128, 2), 256, GEMM_SMEM>>>(
        oh, wo, nullptr, nullptr, nullptr, part, nullptr,
        kD, kD / BKH, kD, kD, kD,
        30, -1, kD / BKH / 2, (long long)SD,
        0, nullptr, 0, nullptr);
    reduce_k<<<(SD + 255) / 256, 256>>>(part, x0h, x1, nullptr, SD);

    // ln1 -> half xn1
    ln_kernel<<<kS, 256>>>(x1, ln1_g, ln1_b, xn1h);

    // gate + aux
    gate_kernel<<<kS, 128>>>(xn1h, gate_w, wdense, varbuf);
    aux_kernel<<<1, 256>>>(varbuf, out + (size_t)out_size - 1);

    // MoE: all-expert w1 -> ha (half)
    gemm_hw<<<dim3(kS / 128, 256), 256, GEMM_SMEM>>>(
        xn1h, w1, w1 + (size_t)KFD, w1 + 2 * (size_t)KFD, w1 + 3 * (size_t)KFD,
        nullptr, hah, kNE * kF, kD / BKH, kD, kD, kNE * kF,
        13, -1, kD / BKH, 0,
        0, nullptr, 0, nullptr);

    // all-expert w3 with fused gate+silu epilogue -> hb (half)
    gemm_hw<<<dim3(kS / 128, 256), 256, GEMM_SMEM>>>(
        xn1h, w3, w3 + (size_t)KFD, w3 + 2 * (size_t)KFD, w3 + 3 * (size_t)KFD,
        nullptr, hbh, kNE * kF, kD / BKH, kD, kD, kNE * kF,
        13, -1, kD / BKH, 0,
        2, hah, kNE * kF, wdense);

    // fused 4-expert w2, K=32768, split-K=2 -> partials; reduce + xn1 residual -> x2
    gemm_hw<<<dim3(kS / 128, kD / 128, 2), 256, GEMM_SMEM>>>(
        hbh, w2, w2 + (size_t)KFD, w2 + 2 * (size_t)KFD, w2 + 3 * (size_t)KFD,
        part, nullptr, kD, (kNE * kF) / BKH, kNE * kF, kF, kD,
        30, 7, (kNE * kF) / BKH / 2, (long long)SD,
        0, nullptr, 0, nullptr);
    reduce_k<<<(SD + 255) / 256, 256>>>(part, xn1h, x2, nullptr, SD);

    // ln2 + final ln -> half x4
    ln2x_kernel<<<kS, 256>>>(x2, ln2_g, ln2_b, fin_g, fin_b, x4h);

    // LM head -> fp32 logits
    gemm_hw<<<dim3(kS / 128, (kVOC + 127) / 128), 256, GEMM_SMEM>>>(
        x4h, head_w, nullptr, nullptr, nullptr, out, nullptr,
        kVOC, kD / BKH, kD, kD, kVOC,
        30, -1, kD / BKH, 0,
        0, nullptr, 0, nullptr);
}

// round 8
// speedup vs baseline: 1.0010x; 1.0010x over previous
#include <cuda_runtime.h>
#include <cuda_fp16.h>
#include <math.h>
#include <stdint.h>

// ---------------- constants ----------------
#define kS   1024
#define kD   2048
#define kH   32
#define kHD  64
#define kF   8192
#define kNE  4
#define kVOC 50257

// ---------------- scratch ----------------
__device__ __half g_wqh[kD*kD];
__device__ __half g_wkh[kD*kD];
__device__ __half g_wvh[kD*kD];
__device__ __half g_woh[kD*kD];
__device__ __half g_w1h[kNE*kF*kD];
__device__ __half g_w3h[kNE*kF*kD];
__device__ __half g_w2h[kNE*kD*kF];
__device__ __half g_hdh[kVOC*kD];
__device__ __half g_x0h [kS*kD];
__device__ __half g_qkvh[kS*3*kD];
__device__ __half g_oh  [kS*kD];
__device__ __half g_xn1h[kS*kD];
__device__ __half g_hah [kS*kNE*kF];
__device__ __half g_hbh [kS*kNE*kF];
__device__ __half g_x4h [kS*kD];
__device__ float g_part[2*kS*3*kD];
__device__ float g_x1 [kS*kD];
__device__ float g_x2 [kS*kD];
__device__ float g_wdense[kS*kNE];
__device__ float g_var[kS];

// ---------------- PTX helpers ----------------
__device__ __forceinline__ uint32_t smem_u32(const void* p) {
    uint32_t a;
    asm("{ .reg .u64 t; cvta.to.shared.u64 t, %1; cvt.u32.u64 %0, t; }" : "=r"(a) : "l"(p));
    return a;
}
__device__ __forceinline__ void cpa16(uint32_t dst, const void* src) {
    asm volatile("cp.async.cg.shared.global [%0], [%1], 16;" :: "r"(dst), "l"(src));
}
#define CPA_COMMIT() asm volatile("cp.async.commit_group;" ::: "memory")
#define CPA_WAIT1()  asm volatile("cp.async.wait_group 1;" ::: "memory")

#define LDSM_X4(r, addr) \
    asm volatile("ldmatrix.sync.aligned.m8n8.x4.shared.b16 {%0,%1,%2,%3}, [%4];" \
        : "=r"((r)[0]), "=r"((r)[1]), "=r"((r)[2]), "=r"((r)[3]) : "r"(addr))

__device__ __forceinline__ void mma_f16(float* c, const uint32_t* a, uint32_t b0, uint32_t b1) {
    asm volatile("mma.sync.aligned.m16n8k16.row.col.f32.f16.f16.f32 "
        "{%0,%1,%2,%3}, {%4,%5,%6,%7}, {%8,%9}, {%0,%1,%2,%3};"
        : "+f"(c[0]), "+f"(c[1]), "+f"(c[2]), "+f"(c[3])
        : "r"(a[0]), "r"(a[1]), "r"(a[2]), "r"(a[3]), "r"(b0), "r"(b1));
}

// ---------------- side convert worker (rides inside gemm/attn launches) ----------------
#define CVT_CHUNK 8192   // float4s per side block
__device__ __forceinline__ void side_cvt(int w, int tid,
    const float* __restrict__ s0, __half* __restrict__ d0, int n0,
    const float* __restrict__ s1, __half* __restrict__ d1, int n1)
{
    int base = w * CVT_CHUNK;
#pragma unroll 4
    for (int it = 0; it < 32; it++) {
        int idx = base + it * 256 + tid;
        const float* s; __half* d;
        if (idx < n0) { s = s0; d = d0; }
        else { idx -= n0; if (idx >= n1) continue; s = s1; d = d1; }
        float4 v = ((const float4*)s)[idx];
        __half2 h0 = __floats2half2_rn(v.x, v.y);
        __half2 h1 = __floats2half2_rn(v.z, v.w);
        uint2 pk;
        pk.x = *reinterpret_cast<uint32_t*>(&h0);
        pk.y = *reinterpret_cast<uint32_t*>(&h1);
        ((uint2*)d)[idx] = pk;
    }
}

// ---------------- fp16 mma.sync NT GEMM (1D grid + interleaved side-convert) ----------------
#define BM 128
#define BN 128
#define BKH 64
#define NSTG 3
#define ASTG 16384
#define STGB 32768
#define GEMM_SMEM (NSTG*STGB)

__global__ void __launch_bounds__(256, 2) gemm_h(
    const __half* __restrict__ A,
    const __half* __restrict__ B0, const __half* __restrict__ B1,
    const __half* __restrict__ B2, const __half* __restrict__ B3,
    float* __restrict__ Cf, __half* __restrict__ Ch,
    int N, int KT, int ldA, int ldB, int ldC,
    int nShift, int kShift, int ktPerZ, long long zStrideC,
    int fmode, const __half* __restrict__ F, int ldF,
    const float* __restrict__ wdense,
    int mT, int nT, int zT,
    const float* __restrict__ cs0, __half* __restrict__ cd0, int cn0,
    const float* __restrict__ cs1, __half* __restrict__ cd1, int cn1)
{
    extern __shared__ char smraw[];
    int tid = threadIdx.x;
    // ---- role select (Bresenham interleave) ----
    int G = mT * nT * zT;
    int total = (int)gridDim.x;
    int C = total - G;
    int bid = blockIdx.x;
    long long lo = (long long)bid * C / total;
    long long hi = ((long long)bid + 1) * C / total;
    if (hi > lo) { side_cvt((int)lo, tid, cs0, cd0, cn0, cs1, cd1, cn1); return; }
    int g = bid - (int)lo;
    int bx = g % mT; g /= mT;
    int by = g % nT;
    int bz = g / nT;

    uint32_t sb = smem_u32(smraw);
    int lane = tid & 31, wid = tid >> 5;
    int wm = wid >> 2, wn = wid & 3;
    int bm = bx * BM, bn = by * BN;

    Cf += (long long)bz * zStrideC;
    int ktBeg = bz * ktPerZ;
    int KTz = KT - ktBeg; if (KTz > ktPerZ) KTz = ktPerZ;

    const __half* BnBase;
    {
        int seg = bn >> nShift;
        const __half* bp = (seg == 0) ? B0 : (seg == 1) ? B1 : (seg == 2) ? B2 : B3;
        BnBase = bp + (size_t)(bn - (seg << nShift)) * ldB;
    }

    auto load_stage = [&](int s, int kt) {
        int ktl = kt;
        const __half* Bb = BnBase;
        if (kShift >= 0) {
            int seg = kt >> kShift;
            const __half* bp = (seg == 0) ? B0 : (seg == 1) ? B1 : (seg == 2) ? B2 : B3;
            ktl = kt - (seg << kShift);
            Bb = bp + (size_t)bn * ldB;
        }
#pragma unroll
        for (int j = 0; j < 8; j++) {
            int idx = tid + j * 256;
            int isB = idx >> 10;
            int un = idx & 1023;
            int row = un >> 3, c = un & 7;
            uint32_t base = sb + (uint32_t)s * STGB + (isB ? ASTG : 0u)
                          + (uint32_t)(row << 7) + ((uint32_t)(c ^ (row & 7)) << 4);
            if (!isB) {
                cpa16(base, A + (size_t)(bm + row) * ldA + kt * BKH + c * 8);
            } else if (bn + row < N) {
                cpa16(base, Bb + (size_t)row * ldB + ktl * BKH + c * 8);
            }
        }
    };

    float acc[4][4][4];
#pragma unroll
    for (int i = 0; i < 4; i++)
#pragma unroll
        for (int j = 0; j < 4; j++)
#pragma unroll
            for (int r = 0; r < 4; r++) acc[i][j][r] = 0.0f;

    int l7 = lane & 7;
    int sub = lane >> 3;
    int arow = (sub & 1) * 8 + l7;
    int ah   = sub >> 1;
    int bnl  = (sub >> 1) * 8 + l7;
    int bch  = sub & 1;
    uint32_t aBase = sb + (uint32_t)((wm * 64 + arow) << 7);
    uint32_t bBase = sb + ASTG + (uint32_t)((wn * 32 + bnl) << 7);

#pragma unroll
    for (int s = 0; s < NSTG - 1; s++) {
        if (s < KTz) load_stage(s, ktBeg + s);
        CPA_COMMIT();
    }

    int scomp = 0, sload = NSTG - 1;
    for (int t = 0; t < KTz; t++) {
        CPA_WAIT1();
        __syncthreads();
        int tn = t + NSTG - 1;
        if (tn < KTz) load_stage(sload, ktBeg + tn);
        CPA_COMMIT();

        uint32_t aS = aBase + (uint32_t)scomp * STGB;
        uint32_t bS = bBase + (uint32_t)scomp * STGB;
#pragma unroll
        for (int ks = 0; ks < 4; ks++) {
            uint32_t bf[2][4];
            uint32_t af[4][4];
#pragma unroll
            for (int ntp = 0; ntp < 2; ntp++)
                LDSM_X4(bf[ntp], bS + (uint32_t)(ntp * 2048) +
                                  ((uint32_t)((2 * ks + bch) ^ l7) << 4));
#pragma unroll
            for (int mt = 0; mt < 4; mt++)
                LDSM_X4(af[mt], aS + (uint32_t)(mt * 2048) +
                                 ((uint32_t)((2 * ks + ah) ^ l7) << 4));
#pragma unroll
            for (int mt = 0; mt < 4; mt++)
#pragma unroll
                for (int nt = 0; nt < 4; nt++)
                    mma_f16(acc[mt][nt], af[mt],
                            bf[nt >> 1][(nt & 1) * 2], bf[nt >> 1][(nt & 1) * 2 + 1]);
        }
        scomp = (scomp + 1 == NSTG) ? 0 : scomp + 1;
        sload = (sload + 1 == NSTG) ? 0 : sload + 1;
    }

    // epilogue
    int evenN = ((N & 1) == 0);
#pragma unroll
    for (int mt = 0; mt < 4; mt++) {
        int r0 = bm + wm * 64 + mt * 16 + (lane >> 2);
        int r1 = r0 + 8;
#pragma unroll
        for (int nt = 0; nt < 4; nt++) {
            int n0 = bn + wn * 32 + nt * 8 + 2 * (lane & 3);
            const float* a = acc[mt][nt];
            float v00 = a[0], v01 = a[1], v10 = a[2], v11 = a[3];
            if (fmode == 2) {
                float2 f0 = __half22float2(*(const __half2*)(F + (size_t)r0 * ldF + n0));
                float2 f1 = __half22float2(*(const __half2*)(F + (size_t)r1 * ldF + n0));
                int e = n0 >> 13;
                float w0 = wdense[r0 * 4 + e], w1_ = wdense[r1 * 4 + e];
                v00 = w0 * (f0.x / (1.0f + __expf(-f0.x))) * v00;
                v01 = w0 * (f0.y / (1.0f + __expf(-f0.y))) * v01;
                v10 = w1_ * (f1.x / (1.0f + __expf(-f1.x))) * v10;
                v11 = w1_ * (f1.y / (1.0f + __expf(-f1.y))) * v11;
            }
            if (Ch) {
                *(__half2*)(Ch + (size_t)r0 * ldC + n0) = __floats2half2_rn(v00, v01);
                *(__half2*)(Ch + (size_t)r1 * ldC + n0) = __floats2half2_rn(v10, v11);
            } else if (evenN && n0 + 1 < N) {
                *(float2*)(Cf + (size_t)r0 * ldC + n0) = make_float2(v00, v01);
                *(float2*)(Cf + (size_t)r1 * ldC + n0) = make_float2(v10, v11);
            } else {
                if (n0 < N)     { Cf[(size_t)r0 * ldC + n0] = v00; Cf[(size_t)r1 * ldC + n0] = v10; }
                if (n0 + 1 < N) { Cf[(size_t)r0 * ldC + n0 + 1] = v01; Cf[(size_t)r1 * ldC + n0 + 1] = v11; }
            }
        }
    }
}

// ---------------- standalone convert ----------------
__global__ void cvt_h(const float* __restrict__ in, __half* __restrict__ out, int n4) {
    int i = blockIdx.x * blockDim.x + threadIdx.x;
    if (i < n4) {
        float4 v = ((const float4*)in)[i];
        __half2 h0 = __floats2half2_rn(v.x, v.y);
        __half2 h1 = __floats2half2_rn(v.z, v.w);
        uint2 pr;
        pr.x = *reinterpret_cast<uint32_t*>(&h0);
        pr.y = *reinterpret_cast<uint32_t*>(&h1);
        ((uint2*)out)[i] = pr;
    }
}

// ---------------- embed (half out) ----------------
__global__ void embed_kernel(const int* __restrict__ tok, const float* __restrict__ emb,
                             __half* __restrict__ X) {
    int i = blockIdx.x * blockDim.x + threadIdx.x;
    int t = i >> 11;
    int d = i & 2047;
    X[i] = __float2half_rn(emb[(size_t)tok[t] * kD + d]);
}

// ---------------- fused split-K reduce + RoPE -> half packed QKV ----------------
__global__ void reduce_rope(const float* __restrict__ P, __half* __restrict__ Q) {
    int i = blockIdx.x * blockDim.x + threadIdx.x;   // pair index, kS*3*kD/2 total
    int col2 = i % (3 * kD / 2);
    int t = i / (3 * kD / 2);
    const size_t n = (size_t)kS * 3 * kD;
    float v0 = P[2 * (size_t)i]     + P[n + 2 * (size_t)i];
    float v1 = P[2 * (size_t)i + 1] + P[n + 2 * (size_t)i + 1];
    int d = col2 * 2;
    if (d < 2 * kD) {   // q or k half: apply rope
        int p = (d & 63) >> 1;
        float inv = 1.0f / powf(10000.0f, (float)(2 * p) / 64.0f);
        float ang = (float)t * inv;
        float c = cosf(ang), s = sinf(ang);
        float r0 = v0 * c - v1 * s;
        float r1 = v0 * s + v1 * c;
        v0 = r0; v1 = r1;
    }
    ((__half2*)Q)[i] = __floats2half2_rn(v0, v1);
}

// ---------------- attention (with side-convert blocks at blockIdx.x >= nbq) ----------------
__global__ void attn_kernel(const __half* __restrict__ QKV, __half* __restrict__ O,
                            const float* __restrict__ cs0, __half* __restrict__ cd0, int cn0,
                            int nbq) {
    extern __shared__ float sm[];
    int tid = threadIdx.x;
    if ((int)blockIdx.x >= nbq) {
        int w = ((int)blockIdx.x - nbq) + ((int)gridDim.x - nbq) * (int)blockIdx.y;
        side_cvt(w, tid, cs0, cd0, cn0, nullptr, nullptr, 0);
        return;
    }
    const int LD = 68;
    const int ldx = 3 * kD;
    float* Qt  = sm;
    float* KP  = Qt + 64 * LD;
    float* Vs  = KP + 64 * LD;
    float* den = Vs + 64 * LD;
    int qi = blockIdx.x;
    int h  = blockIdx.y;
    int tx = tid & 15, ty = tid >> 4;

    for (int it = tid; it < 512; it += 256) {
        int q = it >> 3;
        int c8 = (it & 7) << 3;
        uint4 raw = *(const uint4*)(QKV + (size_t)(qi * 64 + q) * ldx + h * kHD + c8);
        const __half2* hp = (const __half2*)&raw;
#pragma unroll
        for (int m = 0; m < 4; m++) {
            float2 f = __half22float2(hp[m]);
            Qt[(c8 + 2 * m) * LD + q] = f.x;
            Qt[(c8 + 2 * m + 1) * LD + q] = f.y;
        }
    }
    if (tid < 64) den[tid] = 0.0f;

    float o[4][4] = {};
    for (int j = 0; j <= qi; j++) {
        __syncthreads();
        for (int it = tid; it < 512; it += 256) {
            int r = it >> 3;
            int c8 = (it & 7) << 3;
            uint4 kraw = *(const uint4*)(QKV + kD + (size_t)(j * 64 + r) * ldx + h * kHD + c8);
            uint4 vraw = *(const uint4*)(QKV + 2 * kD + (size_t)(j * 64 + r) * ldx + h * kHD + c8);
            const __half2* kp = (const __half2*)&kraw;
            const __half2* vp = (const __half2*)&vraw;
#pragma unroll
            for (int m = 0; m < 4; m++) {
                float2 fk = __half22float2(kp[m]);
                KP[(c8 + 2 * m) * LD + r] = fk.x;
                KP[(c8 + 2 * m + 1) * LD + r] = fk.y;
                float2 fv = __half22float2(vp[m]);
                Vs[r * LD + c8 + 2 * m] = fv.x;
                Vs[r * LD + c8 + 2 * m + 1] = fv.y;
            }
        }
        __syncthreads();
        float s[4][4] = {};
#pragma unroll 8
        for (int d = 0; d < 64; d++) {
            float4 a = *(const float4*)&Qt[d * LD + (ty << 2)];
            float4 b = *(const float4*)&KP[d * LD + (tx << 2)];
            float av[4] = {a.x, a.y, a.z, a.w};
            float bv[4] = {b.x, b.y, b.z, b.w};
#pragma unroll
            for (int i = 0; i < 4; i++)
#pragma unroll
                for (int j2 = 0; j2 < 4; j2++) s[i][j2] += av[i] * bv[j2];
        }
        __syncthreads();
#pragma unroll
        for (int i = 0; i < 4; i++) {
#pragma unroll
            for (int j2 = 0; j2 < 4; j2++) {
                int q = ty * 4 + i;
                int kcol = tx * 4 + j2;
                float val = s[i][j2] * 0.125f;
                if (j == qi && kcol > q) val = -INFINITY;
                KP[kcol * LD + q] = val;
            }
        }
        __syncthreads();
        {
            int q = tid >> 2, part = tid & 3;
            float m = -INFINITY;
#pragma unroll
            for (int i = 0; i < 16; i++)
                m = fmaxf(m, KP[(part + 4 * i) * LD + q]);
            m = fmaxf(m, __shfl_xor_sync(0xFFFFFFFFu, m, 1));
            m = fmaxf(m, __shfl_xor_sync(0xFFFFFFFFu, m, 2));
            float ds = 0.0f;
#pragma unroll
            for (int i = 0; i < 16; i++) {
                int k2 = part + 4 * i;
                float p = __expf(KP[k2 * LD + q] - m);
                KP[k2 * LD + q] = p;
                ds += p;
            }
            ds += __shfl_xor_sync(0xFFFFFFFFu, ds, 1);
            ds += __shfl_xor_sync(0xFFFFFFFFu, ds, 2);
            if (part == 0) den[q] += ds;
        }
        __syncthreads();
#pragma unroll 8
        for (int k2 = 0; k2 < 64; k2++) {
            float4 a = *(const float4*)&KP[k2 * LD + (ty << 2)];
            float4 b = *(const float4*)&Vs[k2 * LD + (tx << 2)];
            float av[4] = {a.x, a.y, a.z, a.w};
            float bv[4] = {b.x, b.y, b.z, b.w};
#pragma unroll
            for (int i = 0; i < 4; i++)
#pragma unroll
                for (int j2 = 0; j2 < 4; j2++) o[i][j2] += av[i] * bv[j2];
        }
    }
    __syncthreads();
#pragma unroll
    for (int i = 0; i < 4; i++) {
        int q = ty * 4 + i;
        float dn = den[q] + 1e-6f;
#pragma unroll
        for (int j2 = 0; j2 < 4; j2++) {
            int d = tx * 4 + j2;
            O[(size_t)(qi * 64 + q) * kD + h * kHD + d] = __float2half_rn(o[i][j2] / dn);
        }
    }
}

// ---------------- split-K reduce: v = P[i] + P[n+i] (+ half residual) ----------------
__global__ void reduce_k(const float* __restrict__ P, const __half* __restrict__ R,
                         float* __restrict__ Cf, __half* __restrict__ Ch, int n) {
    int i = blockIdx.x * blockDim.x + threadIdx.x;
    if (i < n) {
        float v = P[i] + P[(size_t)n + i];
        if (R) v += __half2float(R[i]);
        if (Ch) Ch[i] = __float2half_rn(v);
        else    Cf[i] = v;
    }
}

// ---------------- layernorm (fp32 in, half out) ----------------
__global__ void ln_kernel(const float* __restrict__ X, const float* __restrict__ g,
                          const float* __restrict__ b, __half* __restrict__ Y) {
    int row = blockIdx.x;
    int tid = threadIdx.x;
    __shared__ float red[256];
    __shared__ float s_mu, s_inv;
    const float* x = X + (size_t)row * kD;
    float s = 0.0f;
    for (int i = tid; i < kD; i += 256) s += x[i];
    red[tid] = s; __syncthreads();
    for (int st = 128; st > 0; st >>= 1) { if (tid < st) red[tid] += red[tid + st]; __syncthreads(); }
    if (tid == 0) s_mu = red[0] / (float)kD;
    __syncthreads();
    float mu = s_mu;
    float v = 0.0f;
    for (int i = tid; i < kD; i += 256) { float d = x[i] - mu; v += d * d; }
    red[tid] = v; __syncthreads();
    for (int st = 128; st > 0; st >>= 1) { if (tid < st) red[tid] += red[tid + st]; __syncthreads(); }
    if (tid == 0) s_inv = 1.0f / sqrtf(red[0] / (float)kD + 1e-5f);
    __syncthreads();
    float inv = s_inv;
    for (int i = tid; i < kD; i += 256)
        Y[(size_t)row * kD + i] = __float2half_rn((x[i] - mu) * inv * g[i] + b[i]);
}

// ---------------- fused double layernorm (fp32 in, half out) ----------------
__global__ void ln2x_kernel(const float* __restrict__ X,
                            const float* __restrict__ g2, const float* __restrict__ b2,
                            const float* __restrict__ gf, const float* __restrict__ bf,
                            __half* __restrict__ Y) {
    int row = blockIdx.x;
    int tid = threadIdx.x;
    __shared__ float red[256];
    __shared__ float s_mu, s_inv;
    __shared__ float buf[kD];
    const float* x = X + (size_t)row * kD;
    float s = 0.0f;
    for (int i = tid; i < kD; i += 256) s += x[i];
    red[tid] = s; __syncthreads();
    for (int st = 128; st > 0; st >>= 1) { if (tid < st) red[tid] += red[tid + st]; __syncthreads(); }
    if (tid == 0) s_mu = red[0] / (float)kD;
    __syncthreads();
    float mu = s_mu;
    float v = 0.0f;
    for (int i = tid; i < kD; i += 256) { float d = x[i] - mu; v += d * d; }
    red[tid] = v; __syncthreads();
    for (int st = 128; st > 0; st >>= 1) { if (tid < st) red[tid] += red[tid + st]; __syncthreads(); }
    if (tid == 0) s_inv = 1.0f / sqrtf(red[0] / (float)kD + 1e-5f);
    __syncthreads();
    float inv = s_inv;
    for (int i = tid; i < kD; i += 256)
        buf[i] = (x[i] - mu) * inv * g2[i] + b2[i];
    __syncthreads();
    s = 0.0f;
    for (int i = tid; i < kD; i += 256) s += buf[i];
    red[tid] = s; __syncthreads();
    for (int st = 128; st > 0; st >>= 1) { if (tid < st) red[tid] += red[tid + st]; __syncthreads(); }
    if (tid == 0) s_mu = red[0] / (float)kD;
    __syncthreads();
    mu = s_mu;
    v = 0.0f;
    for (int i = tid; i < kD; i += 256) { float d = buf[i] - mu; v += d * d; }
    red[tid] = v; __syncthreads();
    for (int st = 128; st > 0; st >>= 1) { if (tid < st) red[tid] += red[tid + st]; __syncthreads(); }
    if (tid == 0) s_inv = 1.0f / sqrtf(red[0] / (float)kD + 1e-5f);
    __syncthreads();
    inv = s_inv;
    for (int i = tid; i < kD; i += 256)
        Y[(size_t)row * kD + i] = __float2half_rn((buf[i] - mu) * inv * gf[i] + bf[i]);
}

// ---------------- gate (half X) ----------------
__global__ void gate_kernel(const __half* __restrict__ X, const float* __restrict__ GW,
                            float* __restrict__ wdense, float* __restrict__ varbuf) {
    int t = blockIdx.x;
    int tid = threadIdx.x;
    __shared__ float red[128];
    __shared__ float logits[4];
    const __half* x = X + (size_t)t * kD;
    float acc[4] = {0.f, 0.f, 0.f, 0.f};
    for (int d = tid; d < kD; d += 128) {
        float xv = __half2float(x[d]);
        acc[0] += xv * GW[0 * kD + d];
        acc[1] += xv * GW[1 * kD + d];
        acc[2] += xv * GW[2 * kD + d];
        acc[3] += xv * GW[3 * kD + d];
    }
    for (int e = 0; e < 4; e++) {
        red[tid] = acc[e]; __syncthreads();
        for (int st = 64; st > 0; st >>= 1) { if (tid < st) red[tid] += red[tid + st]; __syncthreads(); }
        if (tid == 0) logits[e] = red[0];
        __syncthreads();
    }
    if (tid == 0) {
        float l[4] = {logits[0], logits[1], logits[2], logits[3]};
        float mx = fmaxf(fmaxf(l[0], l[1]), fmaxf(l[2], l[3]));
        float pe[4], ps = 0.f;
        for (int e = 0; e < 4; e++) { pe[e] = expf(l[e] - mx); ps += pe[e]; }
        float pr[4];
        for (int e = 0; e < 4; e++) pr[e] = pe[e] / ps;
        int a = 0;
        for (int e = 1; e < 4; e++) if (pr[e] > pr[a]) a = e;
        int b2 = -1;
        for (int e = 0; e < 4; e++) { if (e == a) continue; if (b2 < 0 || pr[e] > pr[b2]) b2 = e; }
        float wsum = pr[a] + pr[b2];
        float w[4] = {0.f, 0.f, 0.f, 0.f};
        w[a] = pr[a] / wsum; w[b2] = pr[b2] / wsum;
        for (int e = 0; e < 4; e++) wdense[t * 4 + e] = w[e];
        float mu = 0.25f * (l[0] + l[1] + l[2] + l[3]);
        float vv = 0.f;
        for (int e = 0; e < 4; e++) { float d = l[e] - mu; vv += d * d; }
        varbuf[t] = vv / 3.0f;
    }
}

__global__ void aux_kernel(const float* __restrict__ varbuf, float* __restrict__ out) {
    __shared__ float red[256];
    int tid = threadIdx.x;
    float s = 0.f;
    for (int i = tid; i < kS; i += 256) s += varbuf[i];
    red[tid] = s; __syncthreads();
    for (int st = 128; st > 0; st >>= 1) { if (tid < st) red[tid] += red[tid + st]; __syncthreads(); }
    if (tid == 0) out[0] = red[0] / (float)kS;
}

// ---------------- launch ----------------
extern "C" void kernel_launch(void* const* d_in, const int* in_sizes, int n_in,
                              void* d_out, int out_size) {
    const int*   tokens = (const int*)d_in[0];
    const float* emb    = (const float*)d_in[1];
    const float* wq     = (const float*)d_in[2];
    const float* wk     = (const float*)d_in[3];
    const float* wv     = (const float*)d_in[4];
    const float* wo     = (const float*)d_in[5];
    const float* ln1_g  = (const float*)d_in[6];
    const float* ln1_b  = (const float*)d_in[7];
    const float* gate_w = (const float*)d_in[8];
    const float* w1     = (const float*)d_in[9];
    const float* w2     = (const float*)d_in[10];
    const float* w3     = (const float*)d_in[11];
    const float* ln2_g  = (const float*)d_in[12];
    const float* ln2_b  = (const float*)d_in[13];
    const float* fin_g  = (const float*)d_in[14];
    const float* fin_b  = (const float*)d_in[15];
    const float* head_w = (const float*)d_in[16];
    float* out = (float*)d_out;

    __half *wqh, *wkh, *wvh, *woh, *w1h, *w3h, *w2h, *hdh;
    __half *x0h, *qkvh, *oh, *xn1h, *hah, *hbh, *x4h;
    float *part, *x1, *x2, *wdense, *varbuf;
    cudaGetSymbolAddress((void**)&wqh, g_wqh);
    cudaGetSymbolAddress((void**)&wkh, g_wkh);
    cudaGetSymbolAddress((void**)&wvh, g_wvh);
    cudaGetSymbolAddress((void**)&woh, g_woh);
    cudaGetSymbolAddress((void**)&w1h, g_w1h);
    cudaGetSymbolAddress((void**)&w3h, g_w3h);
    cudaGetSymbolAddress((void**)&w2h, g_w2h);
    cudaGetSymbolAddress((void**)&hdh, g_hdh);
    cudaGetSymbolAddress((void**)&x0h,  g_x0h);
    cudaGetSymbolAddress((void**)&qkvh, g_qkvh);
    cudaGetSymbolAddress((void**)&oh,   g_oh);
    cudaGetSymbolAddress((void**)&xn1h, g_xn1h);
    cudaGetSymbolAddress((void**)&hah,  g_hah);
    cudaGetSymbolAddress((void**)&hbh,  g_hbh);
    cudaGetSymbolAddress((void**)&x4h,  g_x4h);
    cudaGetSymbolAddress((void**)&part, g_part);
    cudaGetSymbolAddress((void**)&x1,  g_x1);
    cudaGetSymbolAddress((void**)&x2,  g_x2);
    cudaGetSymbolAddress((void**)&wdense, g_wdense);
    cudaGetSymbolAddress((void**)&varbuf, g_var);

    const int SD = kS * kD;
    const int KFD = kF * kD;           // 16,777,216 elements per expert weight
    const int nDD4 = kD * kD / 4;      // 1,048,576 float4s
    const int nFD4 = kNE * KFD / 4;    // 16,777,216 float4s (w1/w2/w3 each)
    const int nHD4 = kVOC * kD / 4;    // 25,731,584 float4s (head)
    const int HALF1 = nFD4 / 2;        // 8,388,608

    cudaFuncSetAttribute(gemm_h, cudaFuncAttributeMaxDynamicSharedMemorySize, GEMM_SMEM);

    // upfront: convert wq/wk/wv (needed immediately)
    cvt_h<<<(nDD4 + 255) / 256, 256>>>(wq, wqh, nDD4);
    cvt_h<<<(nDD4 + 255) / 256, 256>>>(wk, wkh, nDD4);
    cvt_h<<<(nDD4 + 255) / 256, 256>>>(wv, wvh, nDD4);

    // embed
    embed_kernel<<<SD / 256, 256>>>(tokens, emb, x0h);

    // QKV gemm (split-K=2) + side: cvt wo + first half of w1
    {
        int G = 8 * 48 * 2;
        int cb = (nDD4 + HALF1 + CVT_CHUNK - 1) / CVT_CHUNK;
        gemm_h<<<G + cb, 256, GEMM_SMEM>>>(
            x0h, wqh, wkh, wvh, nullptr, part, nullptr,
            3 * kD, kD / BKH, kD, kD, 3 * kD,
            11, -1, kD / BKH / 2, (long long)kS * 3 * kD,
            0, nullptr, 0, nullptr,
            8, 48, 2,
            wo, woh, nDD4, w1, w1h, HALF1);
    }
    // fused split-K reduce + rope -> half qkv
    reduce_rope<<<(kS * 3 * kD / 2) / 256, 256>>>(part, qkvh);

    // attention + side: cvt second half of w1
    {
        int attn_smem = (3 * 64 * 68 + 64) * (int)sizeof(float);
        cudaFuncSetAttribute(attn_kernel, cudaFuncAttributeMaxDynamicSharedMemorySize, attn_smem);
        int workers = HALF1 / CVT_CHUNK;               // 1024
        int extraX = (workers + 31) / 32;              // 32
        attn_kernel<<<dim3(16 + extraX, kH), 256, attn_smem>>>(
            qkvh, oh, w1 + (size_t)HALF1 * 4, w1h + (size_t)HALF1 * 4, HALF1, 16);
    }

    // wo gemm (split-K=2) + side: cvt w3 part A (3M float4s)
    {
        int G = 8 * 16 * 2;
        int w3A = 3145728;
        int cb = (w3A + CVT_CHUNK - 1) / CVT_CHUNK;
        gemm_h<<<G + cb, 256, GEMM_SMEM>>>(
            oh, woh, nullptr, nullptr, nullptr, part, nullptr,
            kD, kD / BKH, kD, kD, kD,
            30, -1, kD / BKH / 2, (long long)SD,
            0, nullptr, 0, nullptr,
            8, 16, 2,
            w3, w3h, w3A, nullptr, nullptr, 0);
    }
    reduce_k<<<(SD + 255) / 256, 256>>>(part, x0h, x1, nullptr, SD);

    // ln1 -> half xn1
    ln_kernel<<<kS, 256>>>(x1, ln1_g, ln1_b, xn1h);

    // gate + aux
    gate_kernel<<<kS, 128>>>(xn1h, gate_w, wdense, varbuf);
    aux_kernel<<<1, 256>>>(varbuf, out + (size_t)out_size - 1);

    // w1 gemm + side: cvt rest of w3 + first half of w2
    {
        int G = 8 * 256;
        int w3A = 3145728;
        int w3B = nFD4 - w3A;          // 13,631,488
        int cb = (w3B + HALF1 + CVT_CHUNK - 1) / CVT_CHUNK;
        gemm_h<<<G + cb, 256, GEMM_SMEM>>>(
            xn1h, w1h, w1h + (size_t)KFD, w1h + 2 * (size_t)KFD, w1h + 3 * (size_t)KFD,
            nullptr, hah, kNE * kF, kD / BKH, kD, kD, kNE * kF,
            13, -1, kD / BKH, 0,
            0, nullptr, 0, nullptr,
            8, 256, 1,
            w3 + (size_t)w3A * 4, w3h + (size_t)w3A * 4, w3B,
            w2, w2h, HALF1);
    }

    // w3 gemm (fused silu-gate epilogue) + side: cvt rest of w2 + head part A
    {
        int G = 8 * 256;
        int headA = 6291456;
        int cb = (HALF1 + headA + CVT_CHUNK - 1) / CVT_CHUNK;
        gemm_h<<<G + cb, 256, GEMM_SMEM>>>(
            xn1h, w3h, w3h + (size_t)KFD, w3h + 2 * (size_t)KFD, w3h + 3 * (size_t)KFD,
            nullptr, hbh, kNE * kF, kD / BKH, kD, kD, kNE * kF,
            13, -1, kD / BKH, 0,
            2, hah, kNE * kF, wdense,
            8, 256, 1,
            w2 + (size_t)HALF1 * 4, w2h + (size_t)HALF1 * 4, HALF1,
            head_w, hdh, headA);
    }

    // w2 gemm (K=32768, split-K=2) + side: cvt head part B
    {
        int G = 8 * 16 * 2;
        int headA = 6291456;
        int headB = nHD4 - headA;      // 19,440,128
        int cb = (headB + CVT_CHUNK - 1) / CVT_CHUNK;
        gemm_h<<<G + cb, 256, GEMM_SMEM>>>(
            hbh, w2h, w2h + (size_t)KFD, w2h + 2 * (size_t)KFD, w2h + 3 * (size_t)KFD,
            part, nullptr, kD, (kNE * kF) / BKH, kNE * kF, kF, kD,
            30, 7, (kNE * kF) / BKH / 2, (long long)SD,
            0, nullptr, 0, nullptr,
            8, 16, 2,
            head_w + (size_t)headA * 4, hdh + (size_t)headA * 4, headB,
            nullptr, nullptr, 0);
    }
    reduce_k<<<(SD + 255) / 256, 256>>>(part, xn1h, x2, nullptr, SD);

    // ln2 + final ln -> half x4
    ln2x_kernel<<<kS, 256>>>(x2, ln2_g, ln2_b, fin_g, fin_b, x4h);

    // LM head -> fp32 logits (no sides)
    {
        int nT = (kVOC + 127) / 128;   // 393
        int G = 8 * nT;
        gemm_h<<<G, 256, GEMM_SMEM>>>(
            x4h, hdh, nullptr, nullptr, nullptr, out, nullptr,
            kVOC, kD / BKH, kD, kD, kVOC,
            30, -1, kD / BKH, 0,
            0, nullptr, 0, nullptr,
            8, nT, 1,
            nullptr, nullptr, 0, nullptr, nullptr, 0);
    }
}

// round 9
// speedup vs baseline: 1.1584x; 1.1572x over previous
#include <cuda_runtime.h>
#include <cuda_fp16.h>
#include <math.h>
#include <stdint.h>

// ---------------- constants ----------------
#define kS   1024
#define kD   2048
#define kH   32
#define kHD  64
#define kF   8192
#define kNE  4
#define kVOC 50257

// ---------------- scratch ----------------
__device__ __half g_wqh[kD*kD];
__device__ __half g_wkh[kD*kD];
__device__ __half g_wvh[kD*kD];
__device__ __half g_woh[kD*kD];
__device__ __half g_w1h[kNE*kF*kD];
__device__ __half g_w3h[kNE*kF*kD];
__device__ __half g_w2h[kNE*kD*kF];
__device__ __half g_hdh[kVOC*kD];
__device__ __half g_x0h [kS*kD];
__device__ __half g_qkvh[kS*3*kD];
__device__ __half g_oh  [kS*kD];
__device__ __half g_xn1h[kS*kD];
__device__ __half g_hah [kS*kNE*kF];
__device__ __half g_hbh [kS*kNE*kF];
__device__ __half g_x4h [kS*kD];
__device__ float g_part[2*kS*3*kD];
__device__ float g_wdense[kS*kNE];
__device__ float g_var[kS];

// ---------------- PTX helpers ----------------
__device__ __forceinline__ uint32_t smem_u32(const void* p) {
    uint32_t a;
    asm("{ .reg .u64 t; cvta.to.shared.u64 t, %1; cvt.u32.u64 %0, t; }" : "=r"(a) : "l"(p));
    return a;
}
__device__ __forceinline__ void cpa16(uint32_t dst, const void* src) {
    asm volatile("cp.async.cg.shared.global [%0], [%1], 16;" :: "r"(dst), "l"(src));
}
#define CPA_COMMIT() asm volatile("cp.async.commit_group;" ::: "memory")
#define CPA_WAIT1()  asm volatile("cp.async.wait_group 1;" ::: "memory")

#define LDSM_X4(r, addr) \
    asm volatile("ldmatrix.sync.aligned.m8n8.x4.shared.b16 {%0,%1,%2,%3}, [%4];" \
        : "=r"((r)[0]), "=r"((r)[1]), "=r"((r)[2]), "=r"((r)[3]) : "r"(addr))

__device__ __forceinline__ void mma_f16(float* c, const uint32_t* a, uint32_t b0, uint32_t b1) {
    asm volatile("mma.sync.aligned.m16n8k16.row.col.f32.f16.f16.f32 "
        "{%0,%1,%2,%3}, {%4,%5,%6,%7}, {%8,%9}, {%0,%1,%2,%3};"
        : "+f"(c[0]), "+f"(c[1]), "+f"(c[2]), "+f"(c[3])
        : "r"(a[0]), "r"(a[1]), "r"(a[2]), "r"(a[3]), "r"(b0), "r"(b1));
}

// ---------------- fp16 mma.sync NT GEMM (identical to the 2449us version) -------------
#define BM 128
#define BN 128
#define BKH 64
#define NSTG 3
#define ASTG 16384
#define STGB 32768
#define GEMM_SMEM (NSTG*STGB)

__global__ void __launch_bounds__(256, 2) gemm_h(
    const __half* __restrict__ A,
    const __half* __restrict__ B0, const __half* __restrict__ B1,
    const __half* __restrict__ B2, const __half* __restrict__ B3,
    float* __restrict__ Cf, __half* __restrict__ Ch,
    int N, int KT, int ldA, int ldB, int ldC,
    int nShift, int kShift, int ktPerZ, long long zStrideC,
    int fmode, const __half* __restrict__ F, int ldF,
    const float* __restrict__ wdense)
{
    extern __shared__ char smraw[];
    uint32_t sb = smem_u32(smraw);
    int tid = threadIdx.x, lane = tid & 31, wid = tid >> 5;
    int wm = wid >> 2, wn = wid & 3;
    int bm = blockIdx.x * BM, bn = blockIdx.y * BN;

    Cf += (long long)blockIdx.z * zStrideC;
    int ktBeg = blockIdx.z * ktPerZ;
    int KTz = KT - ktBeg; if (KTz > ktPerZ) KTz = ktPerZ;

    const __half* BnBase;
    {
        int seg = bn >> nShift;
        const __half* bp = (seg == 0) ? B0 : (seg == 1) ? B1 : (seg == 2) ? B2 : B3;
        BnBase = bp + (size_t)(bn - (seg << nShift)) * ldB;
    }

    auto load_stage = [&](int s, int kt) {
        int ktl = kt;
        const __half* Bb = BnBase;
        if (kShift >= 0) {
            int seg = kt >> kShift;
            const __half* bp = (seg == 0) ? B0 : (seg == 1) ? B1 : (seg == 2) ? B2 : B3;
            ktl = kt - (seg << kShift);
            Bb = bp + (size_t)bn * ldB;
        }
#pragma unroll
        for (int j = 0; j < 8; j++) {
            int idx = tid + j * 256;
            int isB = idx >> 10;
            int un = idx & 1023;
            int row = un >> 3, c = un & 7;
            uint32_t base = sb + (uint32_t)s * STGB + (isB ? ASTG : 0u)
                          + (uint32_t)(row << 7) + ((uint32_t)(c ^ (row & 7)) << 4);
            if (!isB) {
                cpa16(base, A + (size_t)(bm + row) * ldA + kt * BKH + c * 8);
            } else if (bn + row < N) {
                cpa16(base, Bb + (size_t)row * ldB + ktl * BKH + c * 8);
            }
        }
    };

    float acc[4][4][4];
#pragma unroll
    for (int i = 0; i < 4; i++)
#pragma unroll
        for (int j = 0; j < 4; j++)
#pragma unroll
            for (int r = 0; r < 4; r++) acc[i][j][r] = 0.0f;

    int l7 = lane & 7;
    int sub = lane >> 3;
    int arow = (sub & 1) * 8 + l7;
    int ah   = sub >> 1;
    int bnl  = (sub >> 1) * 8 + l7;
    int bch  = sub & 1;
    uint32_t aBase = sb + (uint32_t)((wm * 64 + arow) << 7);
    uint32_t bBase = sb + ASTG + (uint32_t)((wn * 32 + bnl) << 7);

#pragma unroll
    for (int s = 0; s < NSTG - 1; s++) {
        if (s < KTz) load_stage(s, ktBeg + s);
        CPA_COMMIT();
    }

    int scomp = 0, sload = NSTG - 1;
    for (int t = 0; t < KTz; t++) {
        CPA_WAIT1();
        __syncthreads();
        int tn = t + NSTG - 1;
        if (tn < KTz) load_stage(sload, ktBeg + tn);
        CPA_COMMIT();

        uint32_t aS = aBase + (uint32_t)scomp * STGB;
        uint32_t bS = bBase + (uint32_t)scomp * STGB;
#pragma unroll
        for (int ks = 0; ks < 4; ks++) {
            uint32_t bf[2][4];
            uint32_t af[4][4];
#pragma unroll
            for (int ntp = 0; ntp < 2; ntp++)
                LDSM_X4(bf[ntp], bS + (uint32_t)(ntp * 2048) +
                                  ((uint32_t)((2 * ks + bch) ^ l7) << 4));
#pragma unroll
            for (int mt = 0; mt < 4; mt++)
                LDSM_X4(af[mt], aS + (uint32_t)(mt * 2048) +
                                 ((uint32_t)((2 * ks + ah) ^ l7) << 4));
#pragma unroll
            for (int mt = 0; mt < 4; mt++)
#pragma unroll
                for (int nt = 0; nt < 4; nt++)
                    mma_f16(acc[mt][nt], af[mt],
                            bf[nt >> 1][(nt & 1) * 2], bf[nt >> 1][(nt & 1) * 2 + 1]);
        }
        scomp = (scomp + 1 == NSTG) ? 0 : scomp + 1;
        sload = (sload + 1 == NSTG) ? 0 : sload + 1;
    }

    int evenN = ((N & 1) == 0);
#pragma unroll
    for (int mt = 0; mt < 4; mt++) {
        int r0 = bm + wm * 64 + mt * 16 + (lane >> 2);
        int r1 = r0 + 8;
#pragma unroll
        for (int nt = 0; nt < 4; nt++) {
            int n0 = bn + wn * 32 + nt * 8 + 2 * (lane & 3);
            const float* a = acc[mt][nt];
            float v00 = a[0], v01 = a[1], v10 = a[2], v11 = a[3];
            if (fmode == 2) {
                float2 f0 = __half22float2(*(const __half2*)(F + (size_t)r0 * ldF + n0));
                float2 f1 = __half22float2(*(const __half2*)(F + (size_t)r1 * ldF + n0));
                int e = n0 >> 13;
                float w0 = wdense[r0 * 4 + e], w1_ = wdense[r1 * 4 + e];
                v00 = w0 * (f0.x / (1.0f + __expf(-f0.x))) * v00;
                v01 = w0 * (f0.y / (1.0f + __expf(-f0.y))) * v01;
                v10 = w1_ * (f1.x / (1.0f + __expf(-f1.x))) * v10;
                v11 = w1_ * (f1.y / (1.0f + __expf(-f1.y))) * v11;
            }
            if (Ch) {
                *(__half2*)(Ch + (size_t)r0 * ldC + n0) = __floats2half2_rn(v00, v01);
                *(__half2*)(Ch + (size_t)r1 * ldC + n0) = __floats2half2_rn(v10, v11);
            } else if (evenN && n0 + 1 < N) {
                *(float2*)(Cf + (size_t)r0 * ldC + n0) = make_float2(v00, v01);
                *(float2*)(Cf + (size_t)r1 * ldC + n0) = make_float2(v10, v11);
            } else {
                if (n0 < N)     { Cf[(size_t)r0 * ldC + n0] = v00; Cf[(size_t)r1 * ldC + n0] = v10; }
                if (n0 + 1 < N) { Cf[(size_t)r0 * ldC + n0 + 1] = v01; Cf[(size_t)r1 * ldC + n0 + 1] = v11; }
            }
        }
    }
}

// ---------------- weight convert fp32 -> fp16 (MLP=4 per thread) ----------------
__global__ void cvt_h(const float* __restrict__ in, __half* __restrict__ out, int n4) {
    int base = blockIdx.x * 1024 + threadIdx.x;
    float4 v[4];
    int ok[4];
#pragma unroll
    for (int j = 0; j < 4; j++) {
        int idx = base + j * 256;
        ok[j] = idx < n4;
        if (ok[j]) v[j] = ((const float4*)in)[idx];
    }
#pragma unroll
    for (int j = 0; j < 4; j++) {
        if (ok[j]) {
            __half2 h0 = __floats2half2_rn(v[j].x, v[j].y);
            __half2 h1 = __floats2half2_rn(v[j].z, v[j].w);
            uint2 pr;
            pr.x = *reinterpret_cast<uint32_t*>(&h0);
            pr.y = *reinterpret_cast<uint32_t*>(&h1);
            ((uint2*)out)[base + j * 256] = pr;
        }
    }
}

// ---------------- embed (half out) ----------------
__global__ void embed_kernel(const int* __restrict__ tok, const float* __restrict__ emb,
                             __half* __restrict__ X) {
    int i = blockIdx.x * blockDim.x + threadIdx.x;
    int t = i >> 11;
    int d = i & 2047;
    X[i] = __float2half_rn(emb[(size_t)tok[t] * kD + d]);
}

// ---------------- fused split-K reduce + RoPE -> half packed QKV ----------------
__global__ void reduce_rope(const float* __restrict__ P, __half* __restrict__ Q) {
    int i = blockIdx.x * blockDim.x + threadIdx.x;   // pair index, kS*3*kD/2 total
    int col2 = i % (3 * kD / 2);
    int t = i / (3 * kD / 2);
    const size_t n = (size_t)kS * 3 * kD;
    float v0 = P[2 * (size_t)i]     + P[n + 2 * (size_t)i];
    float v1 = P[2 * (size_t)i + 1] + P[n + 2 * (size_t)i + 1];
    int d = col2 * 2;
    if (d < 2 * kD) {
        int p = (d & 63) >> 1;
        float inv = 1.0f / powf(10000.0f, (float)(2 * p) / 64.0f);
        float ang = (float)t * inv;
        float c = cosf(ang), s = sinf(ang);
        float r0 = v0 * c - v1 * s;
        float r1 = v0 * s + v1 * c;
        v0 = r0; v1 = r1;
    }
    ((__half2*)Q)[i] = __floats2half2_rn(v0, v1);
}

// ---------------- attention (fp32 compute, half IO, parallel softmax) ----------------
__global__ void attn_kernel(const __half* __restrict__ QKV, __half* __restrict__ O) {
    extern __shared__ float sm[];
    const int LD = 68;
    const int ldx = 3 * kD;
    float* Qt  = sm;
    float* KP  = Qt + 64 * LD;
    float* Vs  = KP + 64 * LD;
    float* den = Vs + 64 * LD;
    int qi = blockIdx.x;
    int h  = blockIdx.y;
    int tid = threadIdx.x;
    int tx = tid & 15, ty = tid >> 4;

    for (int it = tid; it < 512; it += 256) {
        int q = it >> 3;
        int c8 = (it & 7) << 3;
        uint4 raw = *(const uint4*)(QKV + (size_t)(qi * 64 + q) * ldx + h * kHD + c8);
        const __half2* hp = (const __half2*)&raw;
#pragma unroll
        for (int m = 0; m < 4; m++) {
            float2 f = __half22float2(hp[m]);
            Qt[(c8 + 2 * m) * LD + q] = f.x;
            Qt[(c8 + 2 * m + 1) * LD + q] = f.y;
        }
    }
    if (tid < 64) den[tid] = 0.0f;

    float o[4][4] = {};
    for (int j = 0; j <= qi; j++) {
        __syncthreads();
        for (int it = tid; it < 512; it += 256) {
            int r = it >> 3;
            int c8 = (it & 7) << 3;
            uint4 kraw = *(const uint4*)(QKV + kD + (size_t)(j * 64 + r) * ldx + h * kHD + c8);
            uint4 vraw = *(const uint4*)(QKV + 2 * kD + (size_t)(j * 64 + r) * ldx + h * kHD + c8);
            const __half2* kp = (const __half2*)&kraw;
            const __half2* vp = (const __half2*)&vraw;
#pragma unroll
            for (int m = 0; m < 4; m++) {
                float2 fk = __half22float2(kp[m]);
                KP[(c8 + 2 * m) * LD + r] = fk.x;
                KP[(c8 + 2 * m + 1) * LD + r] = fk.y;
                float2 fv = __half22float2(vp[m]);
                Vs[r * LD + c8 + 2 * m] = fv.x;
                Vs[r * LD + c8 + 2 * m + 1] = fv.y;
            }
        }
        __syncthreads();
        float s[4][4] = {};
#pragma unroll 8
        for (int d = 0; d < 64; d++) {
            float4 a = *(const float4*)&Qt[d * LD + (ty << 2)];
            float4 b = *(const float4*)&KP[d * LD + (tx << 2)];
            float av[4] = {a.x, a.y, a.z, a.w};
            float bv[4] = {b.x, b.y, b.z, b.w};
#pragma unroll
            for (int i = 0; i < 4; i++)
#pragma unroll
                for (int j2 = 0; j2 < 4; j2++) s[i][j2] += av[i] * bv[j2];
        }
        __syncthreads();
#pragma unroll
        for (int i = 0; i < 4; i++) {
#pragma unroll
            for (int j2 = 0; j2 < 4; j2++) {
                int q = ty * 4 + i;
                int kcol = tx * 4 + j2;
                float val = s[i][j2] * 0.125f;
                if (j == qi && kcol > q) val = -INFINITY;
                KP[kcol * LD + q] = val;
            }
        }
        __syncthreads();
        {
            int q = tid >> 2, part = tid & 3;
            float m = -INFINITY;
#pragma unroll
            for (int i = 0; i < 16; i++)
                m = fmaxf(m, KP[(part + 4 * i) * LD + q]);
            m = fmaxf(m, __shfl_xor_sync(0xFFFFFFFFu, m, 1));
            m = fmaxf(m, __shfl_xor_sync(0xFFFFFFFFu, m, 2));
            float ds = 0.0f;
#pragma unroll
            for (int i = 0; i < 16; i++) {
                int k2 = part + 4 * i;
                float p = __expf(KP[k2 * LD + q] - m);
                KP[k2 * LD + q] = p;
                ds += p;
            }
            ds += __shfl_xor_sync(0xFFFFFFFFu, ds, 1);
            ds += __shfl_xor_sync(0xFFFFFFFFu, ds, 2);
            if (part == 0) den[q] += ds;
        }
        __syncthreads();
#pragma unroll 8
        for (int k2 = 0; k2 < 64; k2++) {
            float4 a = *(const float4*)&KP[k2 * LD + (ty << 2)];
            float4 b = *(const float4*)&Vs[k2 * LD + (tx << 2)];
            float av[4] = {a.x, a.y, a.z, a.w};
            float bv[4] = {b.x, b.y, b.z, b.w};
#pragma unroll
            for (int i = 0; i < 4; i++)
#pragma unroll
                for (int j2 = 0; j2 < 4; j2++) o[i][j2] += av[i] * bv[j2];
        }
    }
    __syncthreads();
#pragma unroll
    for (int i = 0; i < 4; i++) {
        int q = ty * 4 + i;
        float dn = den[q] + 1e-6f;
#pragma unroll
        for (int j2 = 0; j2 < 4; j2++) {
            int d = tx * 4 + j2;
            O[(size_t)(qi * 64 + q) * kD + h * kHD + d] = __float2half_rn(o[i][j2] / dn);
        }
    }
}

// ---------------- fused: x = P0+P1+R (residual), then LayerNorm -> half ----------------
__global__ void ln_fused(const float* __restrict__ P, const __half* __restrict__ R,
                         const float* __restrict__ g, const float* __restrict__ b,
                         __half* __restrict__ Y) {
    __shared__ float buf[kD];
    __shared__ float red[256];
    __shared__ float s_mu, s_inv;
    int row = blockIdx.x;
    int tid = threadIdx.x;
    const float* p0 = P + (size_t)row * kD;
    const float* p1 = p0 + (size_t)kS * kD;
    const __half* r = R + (size_t)row * kD;
    float s = 0.0f;
    for (int i = tid; i < kD; i += 256) {
        float v = p0[i] + p1[i] + __half2float(r[i]);
        buf[i] = v;
        s += v;
    }
    red[tid] = s; __syncthreads();
    for (int st = 128; st > 0; st >>= 1) { if (tid < st) red[tid] += red[tid + st]; __syncthreads(); }
    if (tid == 0) s_mu = red[0] / (float)kD;
    __syncthreads();
    float mu = s_mu;
    float v = 0.0f;
    for (int i = tid; i < kD; i += 256) { float d = buf[i] - mu; v += d * d; }
    red[tid] = v; __syncthreads();
    for (int st = 128; st > 0; st >>= 1) { if (tid < st) red[tid] += red[tid + st]; __syncthreads(); }
    if (tid == 0) s_inv = 1.0f / sqrtf(red[0] / (float)kD + 1e-5f);
    __syncthreads();
    float inv = s_inv;
    for (int i = tid; i < kD; i += 256)
        Y[(size_t)row * kD + i] = __float2half_rn((buf[i] - mu) * inv * g[i] + b[i]);
}

// ---------------- fused: x = P0+P1+R, LN(ln2), LN(fin) -> half ----------------
__global__ void ln2x_fused(const float* __restrict__ P, const __half* __restrict__ R,
                           const float* __restrict__ g2, const float* __restrict__ b2,
                           const float* __restrict__ gf, const float* __restrict__ bf,
                           __half* __restrict__ Y) {
    __shared__ float buf[kD];
    __shared__ float red[256];
    __shared__ float s_mu, s_inv;
    int row = blockIdx.x;
    int tid = threadIdx.x;
    const float* p0 = P + (size_t)row * kD;
    const float* p1 = p0 + (size_t)kS * kD;
    const __half* r = R + (size_t)row * kD;
    float s = 0.0f;
    for (int i = tid; i < kD; i += 256) {
        float v = p0[i] + p1[i] + __half2float(r[i]);
        buf[i] = v;
        s += v;
    }
    red[tid] = s; __syncthreads();
    for (int st = 128; st > 0; st >>= 1) { if (tid < st) red[tid] += red[tid + st]; __syncthreads(); }
    if (tid == 0) s_mu = red[0] / (float)kD;
    __syncthreads();
    float mu = s_mu;
    float v = 0.0f;
    for (int i = tid; i < kD; i += 256) { float d = buf[i] - mu; v += d * d; }
    red[tid] = v; __syncthreads();
    for (int st = 128; st > 0; st >>= 1) { if (tid < st) red[tid] += red[tid + st]; __syncthreads(); }
    if (tid == 0) s_inv = 1.0f / sqrtf(red[0] / (float)kD + 1e-5f);
    __syncthreads();
    float inv = s_inv;
    for (int i = tid; i < kD; i += 256)
        buf[i] = (buf[i] - mu) * inv * g2[i] + b2[i];
    __syncthreads();
    // second LN
    s = 0.0f;
    for (int i = tid; i < kD; i += 256) s += buf[i];
    red[tid] = s; __syncthreads();
    for (int st = 128; st > 0; st >>= 1) { if (tid < st) red[tid] += red[tid + st]; __syncthreads(); }
    if (tid == 0) s_mu = red[0] / (float)kD;
    __syncthreads();
    mu = s_mu;
    v = 0.0f;
    for (int i = tid; i < kD; i += 256) { float d = buf[i] - mu; v += d * d; }
    red[tid] = v; __syncthreads();
    for (int st = 128; st > 0; st >>= 1) { if (tid < st) red[tid] += red[tid + st]; __syncthreads(); }
    if (tid == 0) s_inv = 1.0f / sqrtf(red[0] / (float)kD + 1e-5f);
    __syncthreads();
    inv = s_inv;
    for (int i = tid; i < kD; i += 256)
        Y[(size_t)row * kD + i] = __float2half_rn((buf[i] - mu) * inv * gf[i] + bf[i]);
}

// ---------------- gate (half X) ----------------
__global__ void gate_kernel(const __half* __restrict__ X, const float* __restrict__ GW,
                            float* __restrict__ wdense, float* __restrict__ varbuf) {
    int t = blockIdx.x;
    int tid = threadIdx.x;
    __shared__ float red[128];
    __shared__ float logits[4];
    const __half* x = X + (size_t)t * kD;
    float acc[4] = {0.f, 0.f, 0.f, 0.f};
    for (int d = tid; d < kD; d += 128) {
        float xv = __half2float(x[d]);
        acc[0] += xv * GW[0 * kD + d];
        acc[1] += xv * GW[1 * kD + d];
        acc[2] += xv * GW[2 * kD + d];
        acc[3] += xv * GW[3 * kD + d];
    }
    for (int e = 0; e < 4; e++) {
        red[tid] = acc[e]; __syncthreads();
        for (int st = 64; st > 0; st >>= 1) { if (tid < st) red[tid] += red[tid + st]; __syncthreads(); }
        if (tid == 0) logits[e] = red[0];
        __syncthreads();
    }
    if (tid == 0) {
        float l[4] = {logits[0], logits[1], logits[2], logits[3]};
        float mx = fmaxf(fmaxf(l[0], l[1]), fmaxf(l[2], l[3]));
        float pe[4], ps = 0.f;
        for (int e = 0; e < 4; e++) { pe[e] = expf(l[e] - mx); ps += pe[e]; }
        float pr[4];
        for (int e = 0; e < 4; e++) pr[e] = pe[e] / ps;
        int a = 0;
        for (int e = 1; e < 4; e++) if (pr[e] > pr[a]) a = e;
        int b2 = -1;
        for (int e = 0; e < 4; e++) { if (e == a) continue; if (b2 < 0 || pr[e] > pr[b2]) b2 = e; }
        float wsum = pr[a] + pr[b2];
        float w[4] = {0.f, 0.f, 0.f, 0.f};
        w[a] = pr[a] / wsum; w[b2] = pr[b2] / wsum;
        for (int e = 0; e < 4; e++) wdense[t * 4 + e] = w[e];
        float mu = 0.25f * (l[0] + l[1] + l[2] + l[3]);
        float vv = 0.f;
        for (int e = 0; e < 4; e++) { float d = l[e] - mu; vv += d * d; }
        varbuf[t] = vv / 3.0f;
    }
}

__global__ void aux_kernel(const float* __restrict__ varbuf, float* __restrict__ out) {
    __shared__ float red[256];
    int tid = threadIdx.x;
    float s = 0.f;
    for (int i = tid; i < kS; i += 256) s += varbuf[i];
    red[tid] = s; __syncthreads();
    for (int st = 128; st > 0; st >>= 1) { if (tid < st) red[tid] += red[tid + st]; __syncthreads(); }
    if (tid == 0) out[0] = red[0] / (float)kS;
}

// ---------------- launch ----------------
extern "C" void kernel_launch(void* const* d_in, const int* in_sizes, int n_in,
                              void* d_out, int out_size) {
    const int*   tokens = (const int*)d_in[0];
    const float* emb    = (const float*)d_in[1];
    const float* wq     = (const float*)d_in[2];
    const float* wk     = (const float*)d_in[3];
    const float* wv     = (const float*)d_in[4];
    const float* wo     = (const float*)d_in[5];
    const float* ln1_g  = (const float*)d_in[6];
    const float* ln1_b  = (const float*)d_in[7];
    const float* gate_w = (const float*)d_in[8];
    const float* w1     = (const float*)d_in[9];
    const float* w2     = (const float*)d_in[10];
    const float* w3     = (const float*)d_in[11];
    const float* ln2_g  = (const float*)d_in[12];
    const float* ln2_b  = (const float*)d_in[13];
    const float* fin_g  = (const float*)d_in[14];
    const float* fin_b  = (const float*)d_in[15];
    const float* head_w = (const float*)d_in[16];
    float* out = (float*)d_out;

    __half *wqh, *wkh, *wvh, *woh, *w1h, *w3h, *w2h, *hdh;
    __half *x0h, *qkvh, *oh, *xn1h, *hah, *hbh, *x4h;
    float *part, *wdense, *varbuf;
    cudaGetSymbolAddress((void**)&wqh, g_wqh);
    cudaGetSymbolAddress((void**)&wkh, g_wkh);
    cudaGetSymbolAddress((void**)&wvh, g_wvh);
    cudaGetSymbolAddress((void**)&woh, g_woh);
    cudaGetSymbolAddress((void**)&w1h, g_w1h);
    cudaGetSymbolAddress((void**)&w3h, g_w3h);
    cudaGetSymbolAddress((void**)&w2h, g_w2h);
    cudaGetSymbolAddress((void**)&hdh, g_hdh);
    cudaGetSymbolAddress((void**)&x0h,  g_x0h);
    cudaGetSymbolAddress((void**)&qkvh, g_qkvh);
    cudaGetSymbolAddress((void**)&oh,   g_oh);
    cudaGetSymbolAddress((void**)&xn1h, g_xn1h);
    cudaGetSymbolAddress((void**)&hah,  g_hah);
    cudaGetSymbolAddress((void**)&hbh,  g_hbh);
    cudaGetSymbolAddress((void**)&x4h,  g_x4h);
    cudaGetSymbolAddress((void**)&part, g_part);
    cudaGetSymbolAddress((void**)&wdense, g_wdense);
    cudaGetSymbolAddress((void**)&varbuf, g_var);

    const int SD = kS * kD;
    const int KFD = kF * kD;

    cudaFuncSetAttribute(gemm_h, cudaFuncAttributeMaxDynamicSharedMemorySize, GEMM_SMEM);

    // ---- convert weights to fp16 (MLP=4 version; 1024 float4s per block) ----
    {
        int nDD = kD * kD / 4;
        cvt_h<<<(nDD + 1023) / 1024, 256>>>(wq, wqh, nDD);
        cvt_h<<<(nDD + 1023) / 1024, 256>>>(wk, wkh, nDD);
        cvt_h<<<(nDD + 1023) / 1024, 256>>>(wv, wvh, nDD);
        cvt_h<<<(nDD + 1023) / 1024, 256>>>(wo, woh, nDD);
        int nFD = kNE * KFD / 4;
        cvt_h<<<(nFD + 1023) / 1024, 256>>>(w1, w1h, nFD);
        cvt_h<<<(nFD + 1023) / 1024, 256>>>(w3, w3h, nFD);
        cvt_h<<<(nFD + 1023) / 1024, 256>>>(w2, w2h, nFD);
        int nHD = kVOC * kD / 4;
        cvt_h<<<(nHD + 1023) / 1024, 256>>>(head_w, hdh, nHD);
    }

    // embed
    embed_kernel<<<SD / 256, 256>>>(tokens, emb, x0h);

    // QKV (split-K=2 -> fp32 partials); fused reduce + rope -> half qkv
    gemm_h<<<dim3(kS / 128, 48, 2), 256, GEMM_SMEM>>>(
        x0h, wqh, wkh, wvh, nullptr, part, nullptr,
        3 * kD, kD / BKH, kD, kD, 3 * kD,
        11, -1, kD / BKH / 2, (long long)kS * 3 * kD,
        0, nullptr, 0, nullptr);
    reduce_rope<<<(kS * 3 * kD / 2) / 256, 256>>>(part, qkvh);

    // attention
    int attn_smem = (3 * 64 * 68 + 64) * (int)sizeof(float);
    cudaFuncSetAttribute(attn_kernel, cudaFuncAttributeMaxDynamicSharedMemorySize, attn_smem);
    attn_kernel<<<dim3(kS / 64, kH), 256, attn_smem>>>(qkvh, oh);

    // wo (split-K=2) -> partials; fused reduce + residual + ln1 -> half xn1
    gemm_h<<<dim3(kS / 128, kD / 128, 2), 256, GEMM_SMEM>>>(
        oh, woh, nullptr, nullptr, nullptr, part, nullptr,
        kD, kD / BKH, kD, kD, kD,
        30, -1, kD / BKH / 2, (long long)SD,
        0, nullptr, 0, nullptr);
    ln_fused<<<kS, 256>>>(part, x0h, ln1_g, ln1_b, xn1h);

    // gate + aux
    gate_kernel<<<kS, 128>>>(xn1h, gate_w, wdense, varbuf);
    aux_kernel<<<1, 256>>>(varbuf, out + (size_t)out_size - 1);

    // MoE: all-expert w1 -> ha (half)
    gemm_h<<<dim3(kS / 128, 256), 256, GEMM_SMEM>>>(
        xn1h, w1h, w1h + (size_t)KFD, w1h + 2 * (size_t)KFD, w1h + 3 * (size_t)KFD,
        nullptr, hah, kNE * kF, kD / BKH, kD, kD, kNE * kF,
        13, -1, kD / BKH, 0,
        0, nullptr, 0, nullptr);

    // all-expert w3 with fused gate+silu epilogue -> hb (half)
    gemm_h<<<dim3(kS / 128, 256), 256, GEMM_SMEM>>>(
        xn1h, w3h, w3h + (size_t)KFD, w3h + 2 * (size_t)KFD, w3h + 3 * (size_t)KFD,
        nullptr, hbh, kNE * kF, kD / BKH, kD, kD, kNE * kF,
        13, -1, kD / BKH, 0,
        2, hah, kNE * kF, wdense);

    // fused 4-expert w2, K=32768, split-K=2 -> partials; fused reduce + residual + 2xLN -> x4
    gemm_h<<<dim3(kS / 128, kD / 128, 2), 256, GEMM_SMEM>>>(
        hbh, w2h, w2h + (size_t)KFD, w2h + 2 * (size_t)KFD, w2h + 3 * (size_t)KFD,
        part, nullptr, kD, (kNE * kF) / BKH, kNE * kF, kF, kD,
        30, 7, (kNE * kF) / BKH / 2, (long long)SD,
        0, nullptr, 0, nullptr);
    ln2x_fused<<<kS, 256>>>(part, xn1h, ln2_g, ln2_b, fin_g, fin_b, x4h);

    // LM head -> fp32 logits
    gemm_h<<<dim3(kS / 128, (kVOC + 127) / 128), 256, GEMM_SMEM>>>(
        x4h, hdh, nullptr, nullptr, nullptr, out, nullptr,
        kVOC, kD / BKH, kD, kD, kVOC,
        30, -1, kD / BKH, 0,
        0, nullptr, 0, nullptr);
}

// round 10
// speedup vs baseline: 1.2589x; 1.0868x over previous
#include <cuda_runtime.h>
#include <cuda_fp16.h>
#include <math.h>
#include <stdint.h>

// ---------------- constants ----------------
#define kS   1024
#define kD   2048
#define kH   32
#define kHD  64
#define kF   8192
#define kNE  4
#define kVOC 50257

// ---------------- scratch ----------------
__device__ __half g_wqh[kD*kD];
__device__ __half g_wkh[kD*kD];
__device__ __half g_wvh[kD*kD];
__device__ __half g_woh[kD*kD];
__device__ __half g_w1h[kNE*kF*kD];
__device__ __half g_w3h[kNE*kF*kD];
__device__ __half g_w2h[kNE*kD*kF];
__device__ __half g_hdh[kVOC*kD];
__device__ __half g_x0h [kS*kD];
__device__ __half g_qkvh[kS*3*kD];
__device__ __half g_oh  [kS*kD];
__device__ __half g_xn1h[kS*kD];
__device__ __half g_hah [kS*kNE*kF];
__device__ __half g_hbh [kS*kNE*kF];
__device__ __half g_x4h [kS*kD];
__device__ float g_part[2*kS*3*kD];
__device__ float g_wdense[kS*kNE];
__device__ float g_var[kS];

// ---------------- PTX helpers ----------------
__device__ __forceinline__ uint32_t smem_u32(const void* p) {
    uint32_t a;
    asm("{ .reg .u64 t; cvta.to.shared.u64 t, %1; cvt.u32.u64 %0, t; }" : "=r"(a) : "l"(p));
    return a;
}
__device__ __forceinline__ void cpa16(uint32_t dst, const void* src) {
    asm volatile("cp.async.cg.shared.global [%0], [%1], 16;" :: "r"(dst), "l"(src));
}
#define CPA_COMMIT() asm volatile("cp.async.commit_group;" ::: "memory")
#define CPA_WAIT1()  asm volatile("cp.async.wait_group 1;" ::: "memory")

#define LDSM_X4(r, addr) \
    asm volatile("ldmatrix.sync.aligned.m8n8.x4.shared.b16 {%0,%1,%2,%3}, [%4];" \
        : "=r"((r)[0]), "=r"((r)[1]), "=r"((r)[2]), "=r"((r)[3]) : "r"(addr))

__device__ __forceinline__ void mma_f16(float* c, const uint32_t* a, uint32_t b0, uint32_t b1) {
    asm volatile("mma.sync.aligned.m16n8k16.row.col.f32.f16.f16.f32 "
        "{%0,%1,%2,%3}, {%4,%5,%6,%7}, {%8,%9}, {%0,%1,%2,%3};"
        : "+f"(c[0]), "+f"(c[1]), "+f"(c[2]), "+f"(c[3])
        : "r"(a[0]), "r"(a[1]), "r"(a[2]), "r"(a[3]), "r"(b0), "r"(b1));
}

// ---------------- fp16 mma.sync NT GEMM: 128x128 tile, 4 warps (2x2), warp 64x64 ------
#define BM 128
#define BN 128
#define BKH 64
#define NSTG 3
#define ASTG 16384
#define STGB 32768
#define GEMM_SMEM (NSTG*STGB)

__global__ void __launch_bounds__(128, 2) gemm_h(
    const __half* __restrict__ A,
    const __half* __restrict__ B0, const __half* __restrict__ B1,
    const __half* __restrict__ B2, const __half* __restrict__ B3,
    float* __restrict__ Cf, __half* __restrict__ Ch,
    int N, int KT, int ldA, int ldB, int ldC,
    int nShift, int kShift, int ktPerZ, long long zStrideC,
    int fmode, const __half* __restrict__ F, int ldF,
    const float* __restrict__ wdense)
{
    extern __shared__ char smraw[];
    uint32_t sb = smem_u32(smraw);
    int tid = threadIdx.x, lane = tid & 31, wid = tid >> 5;
    int wm = wid >> 1, wn = wid & 1;                   // 2x2 warp grid, warp tile 64x64
    int bm = blockIdx.x * BM, bn = blockIdx.y * BN;

    Cf += (long long)blockIdx.z * zStrideC;
    int ktBeg = blockIdx.z * ktPerZ;
    int KTz = KT - ktBeg; if (KTz > ktPerZ) KTz = ktPerZ;

    const __half* BnBase;
    {
        int seg = bn >> nShift;
        const __half* bp = (seg == 0) ? B0 : (seg == 1) ? B1 : (seg == 2) ? B2 : B3;
        BnBase = bp + (size_t)(bn - (seg << nShift)) * ldB;
    }

    auto load_stage = [&](int s, int kt) {
        int ktl = kt;
        const __half* Bb = BnBase;
        if (kShift >= 0) {
            int seg = kt >> kShift;
            const __half* bp = (seg == 0) ? B0 : (seg == 1) ? B1 : (seg == 2) ? B2 : B3;
            ktl = kt - (seg << kShift);
            Bb = bp + (size_t)bn * ldB;
        }
#pragma unroll
        for (int j = 0; j < 16; j++) {
            int idx = tid + j * 128;
            int isB = idx >> 10;
            int un = idx & 1023;
            int row = un >> 3, c = un & 7;
            uint32_t base = sb + (uint32_t)s * STGB + (isB ? ASTG : 0u)
                          + (uint32_t)(row << 7) + ((uint32_t)(c ^ (row & 7)) << 4);
            if (!isB) {
                cpa16(base, A + (size_t)(bm + row) * ldA + kt * BKH + c * 8);
            } else if (bn + row < N) {
                cpa16(base, Bb + (size_t)row * ldB + ktl * BKH + c * 8);
            }
        }
    };

    float acc[4][8][4];
#pragma unroll
    for (int i = 0; i < 4; i++)
#pragma unroll
        for (int j = 0; j < 8; j++)
#pragma unroll
            for (int r = 0; r < 4; r++) acc[i][j][r] = 0.0f;

    int l7 = lane & 7;
    int sub = lane >> 3;
    int arow = (sub & 1) * 8 + l7;
    int ah   = sub >> 1;
    int bnl  = (sub >> 1) * 8 + l7;
    int bch  = sub & 1;
    uint32_t aBase = sb + (uint32_t)((wm * 64 + arow) << 7);
    uint32_t bBase = sb + ASTG + (uint32_t)((wn * 64 + bnl) << 7);

#pragma unroll
    for (int s = 0; s < NSTG - 1; s++) {
        if (s < KTz) load_stage(s, ktBeg + s);
        CPA_COMMIT();
    }

    int scomp = 0, sload = NSTG - 1;
    for (int t = 0; t < KTz; t++) {
        CPA_WAIT1();
        __syncthreads();
        int tn = t + NSTG - 1;
        if (tn < KTz) load_stage(sload, ktBeg + tn);
        CPA_COMMIT();

        uint32_t aS = aBase + (uint32_t)scomp * STGB;
        uint32_t bS = bBase + (uint32_t)scomp * STGB;
#pragma unroll
        for (int ks = 0; ks < 4; ks++) {
            uint32_t bf[4][4];
            uint32_t af[4][4];
#pragma unroll
            for (int ntp = 0; ntp < 4; ntp++)
                LDSM_X4(bf[ntp], bS + (uint32_t)(ntp * 2048) +
                                  ((uint32_t)((2 * ks + bch) ^ l7) << 4));
#pragma unroll
            for (int mt = 0; mt < 4; mt++)
                LDSM_X4(af[mt], aS + (uint32_t)(mt * 2048) +
                                 ((uint32_t)((2 * ks + ah) ^ l7) << 4));
#pragma unroll
            for (int mt = 0; mt < 4; mt++)
#pragma unroll
                for (int nt = 0; nt < 8; nt++)
                    mma_f16(acc[mt][nt], af[mt],
                            bf[nt >> 1][(nt & 1) * 2], bf[nt >> 1][(nt & 1) * 2 + 1]);
        }
        scomp = (scomp + 1 == NSTG) ? 0 : scomp + 1;
        sload = (sload + 1 == NSTG) ? 0 : sload + 1;
    }

    int evenN = ((N & 1) == 0);
#pragma unroll
    for (int mt = 0; mt < 4; mt++) {
        int r0 = bm + wm * 64 + mt * 16 + (lane >> 2);
        int r1 = r0 + 8;
#pragma unroll
        for (int nt = 0; nt < 8; nt++) {
            int n0 = bn + wn * 64 + nt * 8 + 2 * (lane & 3);
            const float* a = acc[mt][nt];
            float v00 = a[0], v01 = a[1], v10 = a[2], v11 = a[3];
            if (fmode == 2) {
                float2 f0 = __half22float2(*(const __half2*)(F + (size_t)r0 * ldF + n0));
                float2 f1 = __half22float2(*(const __half2*)(F + (size_t)r1 * ldF + n0));
                int e = n0 >> 13;
                float w0 = wdense[r0 * 4 + e], w1_ = wdense[r1 * 4 + e];
                v00 = w0 * (f0.x / (1.0f + __expf(-f0.x))) * v00;
                v01 = w0 * (f0.y / (1.0f + __expf(-f0.y))) * v01;
                v10 = w1_ * (f1.x / (1.0f + __expf(-f1.x))) * v10;
                v11 = w1_ * (f1.y / (1.0f + __expf(-f1.y))) * v11;
            }
            if (Ch) {
                *(__half2*)(Ch + (size_t)r0 * ldC + n0) = __floats2half2_rn(v00, v01);
                *(__half2*)(Ch + (size_t)r1 * ldC + n0) = __floats2half2_rn(v10, v11);
            } else if (evenN && n0 + 1 < N) {
                *(float2*)(Cf + (size_t)r0 * ldC + n0) = make_float2(v00, v01);
                *(float2*)(Cf + (size_t)r1 * ldC + n0) = make_float2(v10, v11);
            } else {
                if (n0 < N)     { Cf[(size_t)r0 * ldC + n0] = v00; Cf[(size_t)r1 * ldC + n0] = v10; }
                if (n0 + 1 < N) { Cf[(size_t)r0 * ldC + n0 + 1] = v01; Cf[(size_t)r1 * ldC + n0 + 1] = v11; }
            }
        }
    }
}

// ---------------- weight convert fp32 -> fp16 (MLP=4 per thread) ----------------
__global__ void cvt_h(const float* __restrict__ in, __half* __restrict__ out, int n4) {
    int base = blockIdx.x * 1024 + threadIdx.x;
    float4 v[4];
    int ok[4];
#pragma unroll
    for (int j = 0; j < 4; j++) {
        int idx = base + j * 256;
        ok[j] = idx < n4;
        if (ok[j]) v[j] = ((const float4*)in)[idx];
    }
#pragma unroll
    for (int j = 0; j < 4; j++) {
        if (ok[j]) {
            __half2 h0 = __floats2half2_rn(v[j].x, v[j].y);
            __half2 h1 = __floats2half2_rn(v[j].z, v[j].w);
            uint2 pr;
            pr.x = *reinterpret_cast<uint32_t*>(&h0);
            pr.y = *reinterpret_cast<uint32_t*>(&h1);
            ((uint2*)out)[base + j * 256] = pr;
        }
    }
}

// ---------------- embed (half out) ----------------
__global__ void embed_kernel(const int* __restrict__ tok, const float* __restrict__ emb,
                             __half* __restrict__ X) {
    int i = blockIdx.x * blockDim.x + threadIdx.x;
    int t = i >> 11;
    int d = i & 2047;
    X[i] = __float2half_rn(emb[(size_t)tok[t] * kD + d]);
}

// ---------------- fused split-K reduce + RoPE -> half packed QKV ----------------
__global__ void reduce_rope(const float* __restrict__ P, __half* __restrict__ Q) {
    int i = blockIdx.x * blockDim.x + threadIdx.x;
    int col2 = i % (3 * kD / 2);
    int t = i / (3 * kD / 2);
    const size_t n = (size_t)kS * 3 * kD;
    float v0 = P[2 * (size_t)i]     + P[n + 2 * (size_t)i];
    float v1 = P[2 * (size_t)i + 1] + P[n + 2 * (size_t)i + 1];
    int d = col2 * 2;
    if (d < 2 * kD) {
        int p = (d & 63) >> 1;
        float inv = 1.0f / powf(10000.0f, (float)(2 * p) / 64.0f);
        float ang = (float)t * inv;
        float c = cosf(ang), s = sinf(ang);
        float r0 = v0 * c - v1 * s;
        float r1 = v0 * s + v1 * c;
        v0 = r0; v1 = r1;
    }
    ((__half2*)Q)[i] = __floats2half2_rn(v0, v1);
}

// ---------------- attention (fp32 compute, half IO, parallel softmax) ----------------
__global__ void attn_kernel(const __half* __restrict__ QKV, __half* __restrict__ O) {
    extern __shared__ float sm[];
    const int LD = 68;
    const int ldx = 3 * kD;
    float* Qt  = sm;
    float* KP  = Qt + 64 * LD;
    float* Vs  = KP + 64 * LD;
    float* den = Vs + 64 * LD;
    int qi = blockIdx.x;
    int h  = blockIdx.y;
    int tid = threadIdx.x;
    int tx = tid & 15, ty = tid >> 4;

    for (int it = tid; it < 512; it += 256) {
        int q = it >> 3;
        int c8 = (it & 7) << 3;
        uint4 raw = *(const uint4*)(QKV + (size_t)(qi * 64 + q) * ldx + h * kHD + c8);
        const __half2* hp = (const __half2*)&raw;
#pragma unroll
        for (int m = 0; m < 4; m++) {
            float2 f = __half22float2(hp[m]);
            Qt[(c8 + 2 * m) * LD + q] = f.x;
            Qt[(c8 + 2 * m + 1) * LD + q] = f.y;
        }
    }
    if (tid < 64) den[tid] = 0.0f;

    float o[4][4] = {};
    for (int j = 0; j <= qi; j++) {
        __syncthreads();
        for (int it = tid; it < 512; it += 256) {
            int r = it >> 3;
            int c8 = (it & 7) << 3;
            uint4 kraw = *(const uint4*)(QKV + kD + (size_t)(j * 64 + r) * ldx + h * kHD + c8);
            uint4 vraw = *(const uint4*)(QKV + 2 * kD + (size_t)(j * 64 + r) * ldx + h * kHD + c8);
            const __half2* kp = (const __half2*)&kraw;
            const __half2* vp = (const __half2*)&vraw;
#pragma unroll
            for (int m = 0; m < 4; m++) {
                float2 fk = __half22float2(kp[m]);
                KP[(c8 + 2 * m) * LD + r] = fk.x;
                KP[(c8 + 2 * m + 1) * LD + r] = fk.y;
                float2 fv = __half22float2(vp[m]);
                Vs[r * LD + c8 + 2 * m] = fv.x;
                Vs[r * LD + c8 + 2 * m + 1] = fv.y;
            }
        }
        __syncthreads();
        float s[4][4] = {};
#pragma unroll 8
        for (int d = 0; d < 64; d++) {
            float4 a = *(const float4*)&Qt[d * LD + (ty << 2)];
            float4 b = *(const float4*)&KP[d * LD + (tx << 2)];
            float av[4] = {a.x, a.y, a.z, a.w};
            float bv[4] = {b.x, b.y, b.z, b.w};
#pragma unroll
            for (int i = 0; i < 4; i++)
#pragma unroll
                for (int j2 = 0; j2 < 4; j2++) s[i][j2] += av[i] * bv[j2];
        }
        __syncthreads();
#pragma unroll
        for (int i = 0; i < 4; i++) {
#pragma unroll
            for (int j2 = 0; j2 < 4; j2++) {
                int q = ty * 4 + i;
                int kcol = tx * 4 + j2;
                float val = s[i][j2] * 0.125f;
                if (j == qi && kcol > q) val = -INFINITY;
                KP[kcol * LD + q] = val;
            }
        }
        __syncthreads();
        {
            int q = tid >> 2, part = tid & 3;
            float m = -INFINITY;
#pragma unroll
            for (int i = 0; i < 16; i++)
                m = fmaxf(m, KP[(part + 4 * i) * LD + q]);
            m = fmaxf(m, __shfl_xor_sync(0xFFFFFFFFu, m, 1));
            m = fmaxf(m, __shfl_xor_sync(0xFFFFFFFFu, m, 2));
            float ds = 0.0f;
#pragma unroll
            for (int i = 0; i < 16; i++) {
                int k2 = part + 4 * i;
                float p = __expf(KP[k2 * LD + q] - m);
                KP[k2 * LD + q] = p;
                ds += p;
            }
            ds += __shfl_xor_sync(0xFFFFFFFFu, ds, 1);
            ds += __shfl_xor_sync(0xFFFFFFFFu, ds, 2);
            if (part == 0) den[q] += ds;
        }
        __syncthreads();
#pragma unroll 8
        for (int k2 = 0; k2 < 64; k2++) {
            float4 a = *(const float4*)&KP[k2 * LD + (ty << 2)];
            float4 b = *(const float4*)&Vs[k2 * LD + (tx << 2)];
            float av[4] = {a.x, a.y, a.z, a.w};
            float bv[4] = {b.x, b.y, b.z, b.w};
#pragma unroll
            for (int i = 0; i < 4; i++)
#pragma unroll
                for (int j2 = 0; j2 < 4; j2++) o[i][j2] += av[i] * bv[j2];
        }
    }
    __syncthreads();
#pragma unroll
    for (int i = 0; i < 4; i++) {
        int q = ty * 4 + i;
        float dn = den[q] + 1e-6f;
#pragma unroll
        for (int j2 = 0; j2 < 4; j2++) {
            int d = tx * 4 + j2;
            O[(size_t)(qi * 64 + q) * kD + h * kHD + d] = __float2half_rn(o[i][j2] / dn);
        }
    }
}

// ---------------- fused: x = P0+P1+R (residual), then LayerNorm -> half ----------------
__global__ void ln_fused(const float* __restrict__ P, const __half* __restrict__ R,
                         const float* __restrict__ g, const float* __restrict__ b,
                         __half* __restrict__ Y) {
    __shared__ float buf[kD];
    __shared__ float red[256];
    __shared__ float s_mu, s_inv;
    int row = blockIdx.x;
    int tid = threadIdx.x;
    const float* p0 = P + (size_t)row * kD;
    const float* p1 = p0 + (size_t)kS * kD;
    const __half* r = R + (size_t)row * kD;
    float s = 0.0f;
    for (int i = tid; i < kD; i += 256) {
        float v = p0[i] + p1[i] + __half2float(r[i]);
        buf[i] = v;
        s += v;
    }
    red[tid] = s; __syncthreads();
    for (int st = 128; st > 0; st >>= 1) { if (tid < st) red[tid] += red[tid + st]; __syncthreads(); }
    if (tid == 0) s_mu = red[0] / (float)kD;
    __syncthreads();
    float mu = s_mu;
    float v = 0.0f;
    for (int i = tid; i < kD; i += 256) { float d = buf[i] - mu; v += d * d; }
    red[tid] = v; __syncthreads();
    for (int st = 128; st > 0; st >>= 1) { if (tid < st) red[tid] += red[tid + st]; __syncthreads(); }
    if (tid == 0) s_inv = 1.0f / sqrtf(red[0] / (float)kD + 1e-5f);
    __syncthreads();
    float inv = s_inv;
    for (int i = tid; i < kD; i += 256)
        Y[(size_t)row * kD + i] = __float2half_rn((buf[i] - mu) * inv * g[i] + b[i]);
}

// ---------------- fused: x = P0+P1+R, LN(ln2), LN(fin) -> half ----------------
__global__ void ln2x_fused(const float* __restrict__ P, const __half* __restrict__ R,
                           const float* __restrict__ g2, const float* __restrict__ b2,
                           const float* __restrict__ gf, const float* __restrict__ bf,
                           __half* __restrict__ Y) {
    __shared__ float buf[kD];
    __shared__ float red[256];
    __shared__ float s_mu, s_inv;
    int row = blockIdx.x;
    int tid = threadIdx.x;
    const float* p0 = P + (size_t)row * kD;
    const float* p1 = p0 + (size_t)kS * kD;
    const __half* r = R + (size_t)row * kD;
    float s = 0.0f;
    for (int i = tid; i < kD; i += 256) {
        float v = p0[i] + p1[i] + __half2float(r[i]);
        buf[i] = v;
        s += v;
    }
    red[tid] = s; __syncthreads();
    for (int st = 128; st > 0; st >>= 1) { if (tid < st) red[tid] += red[tid + st]; __syncthreads(); }
    if (tid == 0) s_mu = red[0] / (float)kD;
    __syncthreads();
    float mu = s_mu;
    float v = 0.0f;
    for (int i = tid; i < kD; i += 256) { float d = buf[i] - mu; v += d * d; }
    red[tid] = v; __syncthreads();
    for (int st = 128; st > 0; st >>= 1) { if (tid < st) red[tid] += red[tid + st]; __syncthreads(); }
    if (tid == 0) s_inv = 1.0f / sqrtf(red[0] / (float)kD + 1e-5f);
    __syncthreads();
    float inv = s_inv;
    for (int i = tid; i < kD; i += 256)
        buf[i] = (buf[i] - mu) * inv * g2[i] + b2[i];
    __syncthreads();
    s = 0.0f;
    for (int i = tid; i < kD; i += 256) s += buf[i];
    red[tid] = s; __syncthreads();
    for (int st = 128; st > 0; st >>= 1) { if (tid < st) red[tid] += red[tid + st]; __syncthreads(); }
    if (tid == 0) s_mu = red[0] / (float)kD;
    __syncthreads();
    mu = s_mu;
    v = 0.0f;
    for (int i = tid; i < kD; i += 256) { float d = buf[i] - mu; v += d * d; }
    red[tid] = v; __syncthreads();
    for (int st = 128; st > 0; st >>= 1) { if (tid < st) red[tid] += red[tid + st]; __syncthreads(); }
    if (tid == 0) s_inv = 1.0f / sqrtf(red[0] / (float)kD + 1e-5f);
    __syncthreads();
    inv = s_inv;
    for (int i = tid; i < kD; i += 256)
        Y[(size_t)row * kD + i] = __float2half_rn((buf[i] - mu) * inv * gf[i] + bf[i]);
}

// ---------------- gate (half X) ----------------
__global__ void gate_kernel(const __half* __restrict__ X, const float* __restrict__ GW,
                            float* __restrict__ wdense, float* __restrict__ varbuf) {
    int t = blockIdx.x;
    int tid = threadIdx.x;
    __shared__ float red[128];
    __shared__ float logits[4];
    const __half* x = X + (size_t)t * kD;
    float acc[4] = {0.f, 0.f, 0.f, 0.f};
    for (int d = tid; d < kD; d += 128) {
        float xv = __half2float(x[d]);
        acc[0] += xv * GW[0 * kD + d];
        acc[1] += xv * GW[1 * kD + d];
        acc[2] += xv * GW[2 * kD + d];
        acc[3] += xv * GW[3 * kD + d];
    }
    for (int e = 0; e < 4; e++) {
        red[tid] = acc[e]; __syncthreads();
        for (int st = 64; st > 0; st >>= 1) { if (tid < st) red[tid] += red[tid + st]; __syncthreads(); }
        if (tid == 0) logits[e] = red[0];
        __syncthreads();
    }
    if (tid == 0) {
        float l[4] = {logits[0], logits[1], logits[2], logits[3]};
        float mx = fmaxf(fmaxf(l[0], l[1]), fmaxf(l[2], l[3]));
        float pe[4], ps = 0.f;
        for (int e = 0; e < 4; e++) { pe[e] = expf(l[e] - mx); ps += pe[e]; }
        float pr[4];
        for (int e = 0; e < 4; e++) pr[e] = pe[e] / ps;
        int a = 0;
        for (int e = 1; e < 4; e++) if (pr[e] > pr[a]) a = e;
        int b2 = -1;
        for (int e = 0; e < 4; e++) { if (e == a) continue; if (b2 < 0 || pr[e] > pr[b2]) b2 = e; }
        float wsum = pr[a] + pr[b2];
        float w[4] = {0.f, 0.f, 0.f, 0.f};
        w[a] = pr[a] / wsum; w[b2] = pr[b2] / wsum;
        for (int e = 0; e < 4; e++) wdense[t * 4 + e] = w[e];
        float mu = 0.25f * (l[0] + l[1] + l[2] + l[3]);
        float vv = 0.f;
        for (int e = 0; e < 4; e++) { float d = l[e] - mu; vv += d * d; }
        varbuf[t] = vv / 3.0f;
    }
}

__global__ void aux_kernel(const float* __restrict__ varbuf, float* __restrict__ out) {
    __shared__ float red[256];
    int tid = threadIdx.x;
    float s = 0.f;
    for (int i = tid; i < kS; i += 256) s += varbuf[i];
    red[tid] = s; __syncthreads();
    for (int st = 128; st > 0; st >>= 1) { if (tid < st) red[tid] += red[tid + st]; __syncthreads(); }
    if (tid == 0) out[0] = red[0] / (float)kS;
}

// ---------------- launch ----------------
extern "C" void kernel_launch(void* const* d_in, const int* in_sizes, int n_in,
                              void* d_out, int out_size) {
    const int*   tokens = (const int*)d_in[0];
    const float* emb    = (const float*)d_in[1];
    const float* wq     = (const float*)d_in[2];
    const float* wk     = (const float*)d_in[3];
    const float* wv     = (const float*)d_in[4];
    const float* wo     = (const float*)d_in[5];
    const float* ln1_g  = (const float*)d_in[6];
    const float* ln1_b  = (const float*)d_in[7];
    const float* gate_w = (const float*)d_in[8];
    const float* w1     = (const float*)d_in[9];
    const float* w2     = (const float*)d_in[10];
    const float* w3     = (const float*)d_in[11];
    const float* ln2_g  = (const float*)d_in[12];
    const float* ln2_b  = (const float*)d_in[13];
    const float* fin_g  = (const float*)d_in[14];
    const float* fin_b  = (const float*)d_in[15];
    const float* head_w = (const float*)d_in[16];
    float* out = (float*)d_out;

    __half *wqh, *wkh, *wvh, *woh, *w1h, *w3h, *w2h, *hdh;
    __half *x0h, *qkvh, *oh, *xn1h, *hah, *hbh, *x4h;
    float *part, *wdense, *varbuf;
    cudaGetSymbolAddress((void**)&wqh, g_wqh);
    cudaGetSymbolAddress((void**)&wkh, g_wkh);
    cudaGetSymbolAddress((void**)&wvh, g_wvh);
    cudaGetSymbolAddress((void**)&woh, g_woh);
    cudaGetSymbolAddress((void**)&w1h, g_w1h);
    cudaGetSymbolAddress((void**)&w3h, g_w3h);
    cudaGetSymbolAddress((void**)&w2h, g_w2h);
    cudaGetSymbolAddress((void**)&hdh, g_hdh);
    cudaGetSymbolAddress((void**)&x0h,  g_x0h);
    cudaGetSymbolAddress((void**)&qkvh, g_qkvh);
    cudaGetSymbolAddress((void**)&oh,   g_oh);
    cudaGetSymbolAddress((void**)&xn1h, g_xn1h);
    cudaGetSymbolAddress((void**)&hah,  g_hah);
    cudaGetSymbolAddress((void**)&hbh,  g_hbh);
    cudaGetSymbolAddress((void**)&x4h,  g_x4h);
    cudaGetSymbolAddress((void**)&part, g_part);
    cudaGetSymbolAddress((void**)&wdense, g_wdense);
    cudaGetSymbolAddress((void**)&varbuf, g_var);

    const int SD = kS * kD;
    const int KFD = kF * kD;

    cudaFuncSetAttribute(gemm_h, cudaFuncAttributeMaxDynamicSharedMemorySize, GEMM_SMEM);

    // ---- convert weights to fp16 ----
    {
        int nDD = kD * kD / 4;
        cvt_h<<<(nDD + 1023) / 1024, 256>>>(wq, wqh, nDD);
        cvt_h<<<(nDD + 1023) / 1024, 256>>>(wk, wkh, nDD);
        cvt_h<<<(nDD + 1023) / 1024, 256>>>(wv, wvh, nDD);
        cvt_h<<<(nDD + 1023) / 1024, 256>>>(wo, woh, nDD);
        int nFD = kNE * KFD / 4;
        cvt_h<<<(nFD + 1023) / 1024, 256>>>(w1, w1h, nFD);
        cvt_h<<<(nFD + 1023) / 1024, 256>>>(w3, w3h, nFD);
        cvt_h<<<(nFD + 1023) / 1024, 256>>>(w2, w2h, nFD);
        int nHD = kVOC * kD / 4;
        cvt_h<<<(nHD + 1023) / 1024, 256>>>(head_w, hdh, nHD);
    }

    // embed
    embed_kernel<<<SD / 256, 256>>>(tokens, emb, x0h);

    // QKV (split-K=2 -> fp32 partials); fused reduce + rope -> half qkv
    gemm_h<<<dim3(kS / 128, 48, 2), 128, GEMM_SMEM>>>(
        x0h, wqh, wkh, wvh, nullptr, part, nullptr,
        3 * kD, kD / BKH, kD, kD, 3 * kD,
        11, -1, kD / BKH / 2, (long long)kS * 3 * kD,
        0, nullptr, 0, nullptr);
    reduce_rope<<<(kS * 3 * kD / 2) / 256, 256>>>(part, qkvh);

    // attention
    int attn_smem = (3 * 64 * 68 + 64) * (int)sizeof(float);
    cudaFuncSetAttribute(attn_kernel, cudaFuncAttributeMaxDynamicSharedMemorySize, attn_smem);
    attn_kernel<<<dim3(kS / 64, kH), 256, attn_smem>>>(qkvh, oh);

    // wo (split-K=2) -> partials; fused reduce + residual + ln1 -> half xn1
    gemm_h<<<dim3(kS / 128, kD / 128, 2), 128, GEMM_SMEM>>>(
        oh, woh, nullptr, nullptr, nullptr, part, nullptr,
        kD, kD / BKH, kD, kD, kD,
        30, -1, kD / BKH / 2, (long long)SD,
        0, nullptr, 0, nullptr);
    ln_fused<<<kS, 256>>>(part, x0h, ln1_g, ln1_b, xn1h);

    // gate + aux
    gate_kernel<<<kS, 128>>>(xn1h, gate_w, wdense, varbuf);
    aux_kernel<<<1, 256>>>(varbuf, out + (size_t)out_size - 1);

    // MoE: all-expert w1 -> ha (half)
    gemm_h<<<dim3(kS / 128, 256), 128, GEMM_SMEM>>>(
        xn1h, w1h, w1h + (size_t)KFD, w1h + 2 * (size_t)KFD, w1h + 3 * (size_t)KFD,
        nullptr, hah, kNE * kF, kD / BKH, kD, kD, kNE * kF,
        13, -1, kD / BKH, 0,
        0, nullptr, 0, nullptr);

    // all-expert w3 with fused gate+silu epilogue -> hb (half)
    gemm_h<<<dim3(kS / 128, 256), 128, GEMM_SMEM>>>(
        xn1h, w3h, w3h + (size_t)KFD, w3h + 2 * (size_t)KFD, w3h + 3 * (size_t)KFD,
        nullptr, hbh, kNE * kF, kD / BKH, kD, kD, kNE * kF,
        13, -1, kD / BKH, 0,
        2, hah, kNE * kF, wdense);

    // fused 4-expert w2, K=32768, split-K=2 -> partials; fused reduce + residual + 2xLN -> x4
    gemm_h<<<dim3(kS / 128, kD / 128, 2), 128, GEMM_SMEM>>>(
        hbh, w2h, w2h + (size_t)KFD, w2h + 2 * (size_t)KFD, w2h + 3 * (size_t)KFD,
        part, nullptr, kD, (kNE * kF) / BKH, kNE * kF, kF, kD,
        30, 7, (kNE * kF) / BKH / 2, (long long)SD,
        0, nullptr, 0, nullptr);
    ln2x_fused<<<kS, 256>>>(part, xn1h, ln2_g, ln2_b, fin_g, fin_b, x4h);

    // LM head -> fp32 logits
    gemm_h<<<dim3(kS / 128, (kVOC + 127) / 128), 128, GEMM_SMEM>>>(
        x4h, hdh, nullptr, nullptr, nullptr, out, nullptr,
        kVOC, kD / BKH, kD, kD, kVOC,
        30, -1, kD / BKH, 0,
        0, nullptr, 0, nullptr);
}